// round 13
// baseline (speedup 1.0000x reference)
#include <cuda_runtime.h>
#include <cstdint>

#define B_    128
#define S_    512
#define H_    1024
#define MID_  512
#define E_    512
#define XE_   64
#define FEAT_ 576
#define H4_   4096
#define NBLK  296
#define NTHR  256

typedef unsigned long long u64;

// ---------------- persistent state + scratch (device globals; no allocs) ----------------
__device__ float g_h1[B_ * H_];
__device__ float g_c1[B_ * H_];
__device__ float g_h2[B_ * H_];
__device__ float g_c2[B_ * H_];
__device__ float g_zbb[B_ * MID_];
__device__ float g_mh[B_ * H_];
__device__ float g_z1p0[B_ * H4_];
__device__ float g_z1p1[B_ * H4_];
__device__ float g_x2[B_ * H_];
__device__ float g_mx2[B_ * H_];
__device__ float g_mh2[B_ * H_];
__device__ float g_z2[B_ * H4_];
__device__ float g_z2p0[B_ * H4_];
__device__ float g_z2p1[B_ * H4_];
__device__ float g_s[B_];
__device__ unsigned g_bar_count = 0;
__device__ unsigned g_bar_gen = 0;
// precomputed x-side results for ALL steps (input-only dependent)
__device__ float g_zba_all[S_ * B_ * MID_];   // 134 MB
__device__ float g_mx_all[S_ * B_ * H_];      // 268 MB
__device__ float g_z1_all[S_ * B_ * H4_];     // 1.07 GB

__device__ __forceinline__ float sigf(float x) { return 1.f / (1.f + expf(-x)); }
// L2-only loads for cross-block data (L1 persists within a persistent kernel -> stale otherwise)
__device__ __forceinline__ float4 cg4(const float* p) { return __ldcg((const float4*)p); }
__device__ __forceinline__ float  cg1(const float* p) { return __ldcg(p); }

// packed fp32x2 FMA (sm_100+): doubles fma-pipe flops per issue slot
#define FMA2(acc, a, b) asm("fma.rn.f32x2 %0, %1, %2, %0;" : "+l"(acc) : "l"(a), "l"(b))
#define PACK2(d, f)     asm("mov.b64 %0, {%1, %1};" : "=l"(d) : "r"(__float_as_uint(f)))
#define UNPACK2(lo, hi, v) asm("mov.b64 {%0, %1}, %2;" : "=r"(lo), "=r"(hi) : "l"(v))

// ---------------- grid-wide barrier (all NBLK blocks co-resident: 2 CTAs x 148 SMs) ----------------
__device__ __forceinline__ void grid_barrier(unsigned& gen) {
    __syncthreads();
    if (threadIdx.x == 0) {
        __threadfence();
        unsigned arrived = atomicAdd(&g_bar_count, 1u) + 1u;
        if (arrived == (unsigned)NBLK) {
            g_bar_count = 0;
            __threadfence();
            atomicExch(&g_bar_gen, gen + 1u);
        } else {
            unsigned cur;
            do {
                __nanosleep(64);
                asm volatile("ld.global.cg.u32 %0, [%1];" : "=r"(cur) : "l"(&g_bar_gen));
            } while (cur == gen);
        }
        __threadfence();
    }
    __syncthreads();
    gen++;
}

// ---------------- A-tile loaders ----------------
struct BufLoader {
    const float* A; int lda;
    __device__ __forceinline__ float4 ld(int m, int k) const {
        return cg4(A + (size_t)m * lda + k);
    }
};
struct MulLoader {  // A[m][k] = X[m][k] * Y[m][k], both [*, H_] (pre-offset by m0/koff)
    const float* X; const float* Y;
    __device__ __forceinline__ float4 ld(int m, int k) const {
        float4 a = cg4(X + (size_t)m * H_ + k);
        float4 b = cg4(Y + (size_t)m * H_ + k);
        return make_float4(a.x * b.x, a.y * b.y, a.z * b.z, a.w * b.w);
    }
};
struct EmbLoader {  // gathered embedding row: [word_emb | extra_emb] (read-only tables, L1 ok)
    const float* we; const float* ee; const int* sw; const int* se;
    __device__ __forceinline__ float4 ld(int m, int k) const {
        if (k < E_) return *(const float4*)(we + (size_t)sw[m] * E_ + k);
        return *(const float4*)(ee + (size_t)se[m] * XE_ + (k - E_));
    }
};

typedef float SmA[16][128];
typedef float SmW[16][64];
typedef float Sm64[16][64];

// ---------------- 128x64 tile GEMM (EXACT R8 version, proven best for 1-CTA/SM waves) ----------------
template <class AL>
__device__ __forceinline__ void gemm_seg(u64 (&acc)[4][4], const AL& al,
                                         const float* __restrict__ W, int K,
                                         SmA* As, SmW* Ws) {
    const int tid = threadIdx.x;
    const int lm  = tid >> 2;
    const int lk  = (tid & 3) << 2;
    const int tm  = tid >> 4;
    const int tn  = tid & 15;
    float4 a0 = al.ld(lm, lk);
    float4 a1 = al.ld(lm + 64, lk);
    float4 w  = *(const float4*)(W + (size_t)lm * K + lk);
    const int nch = K >> 4;
    int buf = 0;
    for (int ch = 0; ch < nch; ch++) {
        As[buf][lk + 0][lm] = a0.x; As[buf][lk + 1][lm] = a0.y;
        As[buf][lk + 2][lm] = a0.z; As[buf][lk + 3][lm] = a0.w;
        As[buf][lk + 0][lm + 64] = a1.x; As[buf][lk + 1][lm + 64] = a1.y;
        As[buf][lk + 2][lm + 64] = a1.z; As[buf][lk + 3][lm + 64] = a1.w;
        Ws[buf][lk + 0][lm] = w.x; Ws[buf][lk + 1][lm] = w.y;
        Ws[buf][lk + 2][lm] = w.z; Ws[buf][lk + 3][lm] = w.w;
        __syncthreads();
        if (ch + 1 < nch) {
            a0 = al.ld(lm, ((ch + 1) << 4) + lk);
            a1 = al.ld(lm + 64, ((ch + 1) << 4) + lk);
            w  = *(const float4*)(W + (size_t)lm * K + ((ch + 1) << 4) + lk);
        }
#pragma unroll
        for (int kk = 0; kk < 16; kk++) {
            ulonglong2 ar0 = *(const ulonglong2*)&As[buf][kk][tm << 3];
            ulonglong2 ar1 = *(const ulonglong2*)&As[buf][kk][(tm << 3) + 4];
            float4 wv = *(const float4*)&Ws[buf][kk][tn << 2];
            u64 wp;
            PACK2(wp, wv.x);
            FMA2(acc[0][0], ar0.x, wp); FMA2(acc[0][1], ar0.y, wp);
            FMA2(acc[0][2], ar1.x, wp); FMA2(acc[0][3], ar1.y, wp);
            PACK2(wp, wv.y);
            FMA2(acc[1][0], ar0.x, wp); FMA2(acc[1][1], ar0.y, wp);
            FMA2(acc[1][2], ar1.x, wp); FMA2(acc[1][3], ar1.y, wp);
            PACK2(wp, wv.z);
            FMA2(acc[2][0], ar0.x, wp); FMA2(acc[2][1], ar0.y, wp);
            FMA2(acc[2][2], ar1.x, wp); FMA2(acc[2][3], ar1.y, wp);
            PACK2(wp, wv.w);
            FMA2(acc[3][0], ar0.x, wp); FMA2(acc[3][1], ar0.y, wp);
            FMA2(acc[3][2], ar1.x, wp); FMA2(acc[3][3], ar1.y, wp);
        }
        buf ^= 1;
    }
    __syncthreads();
}

__device__ __forceinline__ void store_tile(float* __restrict__ C, int ldc, int c0,
                                           u64 (&acc)[4][4], const float* __restrict__ bias) {
    const int tid = threadIdx.x;
    const int tm = tid >> 4, tn = tid & 15;
    float4 bv = make_float4(0.f, 0.f, 0.f, 0.f);
    if (bias) bv = *(const float4*)(bias + (tn << 2));
#pragma unroll
    for (int rp = 0; rp < 4; rp++) {
        unsigned l0, h0, l1, h1, l2, h2, l3, h3;
        UNPACK2(l0, h0, acc[0][rp]);
        UNPACK2(l1, h1, acc[1][rp]);
        UNPACK2(l2, h2, acc[2][rp]);
        UNPACK2(l3, h3, acc[3][rp]);
        const int r0 = (tm << 3) + (rp << 1);
        *(float4*)(C + (size_t)r0 * ldc + c0 + (tn << 2)) =
            make_float4(__uint_as_float(l0) + bv.x, __uint_as_float(l1) + bv.y,
                        __uint_as_float(l2) + bv.z, __uint_as_float(l3) + bv.w);
        *(float4*)(C + (size_t)(r0 + 1) * ldc + c0 + (tn << 2)) =
            make_float4(__uint_as_float(h0) + bv.x, __uint_as_float(h1) + bv.y,
                        __uint_as_float(h2) + bv.z, __uint_as_float(h3) + bv.w);
    }
}

// ---------------- 64x64 tile GEMM (R9 version; identical per-element k-order) ----------------
// Used ONLY for M-half pairs placed on the same SM (blocks b and b+148 -> LUT[b%148]).
template <class AL>
__device__ __forceinline__ void gemm64(u64 (&acc)[4][2], const AL& al,
                                       const float* __restrict__ W, int K,
                                       Sm64* As, Sm64* Ws) {
    const int tid = threadIdx.x;
    const int lm  = tid >> 2;
    const int lk  = (tid & 3) << 2;
    const int tm  = tid >> 4;
    const int tn  = tid & 15;
    float4 a = al.ld(lm, lk);
    float4 w = *(const float4*)(W + (size_t)lm * K + lk);
    const int nch = K >> 4;
    int buf = 0;
    for (int ch = 0; ch < nch; ch++) {
        As[buf][lk + 0][lm] = a.x; As[buf][lk + 1][lm] = a.y;
        As[buf][lk + 2][lm] = a.z; As[buf][lk + 3][lm] = a.w;
        Ws[buf][lk + 0][lm] = w.x; Ws[buf][lk + 1][lm] = w.y;
        Ws[buf][lk + 2][lm] = w.z; Ws[buf][lk + 3][lm] = w.w;
        __syncthreads();
        if (ch + 1 < nch) {
            a = al.ld(lm, ((ch + 1) << 4) + lk);
            w = *(const float4*)(W + (size_t)lm * K + ((ch + 1) << 4) + lk);
        }
#pragma unroll
        for (int kk = 0; kk < 16; kk++) {
            float4 a4 = *(const float4*)&As[buf][kk][tm << 2];
            ulonglong2 wp = *(const ulonglong2*)&Ws[buf][kk][tn << 2];
            u64 ap;
            PACK2(ap, a4.x); FMA2(acc[0][0], ap, wp.x); FMA2(acc[0][1], ap, wp.y);
            PACK2(ap, a4.y); FMA2(acc[1][0], ap, wp.x); FMA2(acc[1][1], ap, wp.y);
            PACK2(ap, a4.z); FMA2(acc[2][0], ap, wp.x); FMA2(acc[2][1], ap, wp.y);
            PACK2(ap, a4.w); FMA2(acc[3][0], ap, wp.x); FMA2(acc[3][1], ap, wp.y);
        }
        buf ^= 1;
    }
    __syncthreads();
}

__device__ __forceinline__ void store_tile64(float* __restrict__ C, int ldc, int m0, int c0,
                                             u64 (&acc)[4][2], const float* __restrict__ bias) {
    const int tid = threadIdx.x;
    const int tm = tid >> 4, tn = tid & 15;
    float4 bv = make_float4(0.f, 0.f, 0.f, 0.f);
    if (bias) bv = *(const float4*)(bias + (tn << 2));
#pragma unroll
    for (int i = 0; i < 4; i++) {
        unsigned l0, h0, l1, h1;
        UNPACK2(l0, h0, acc[i][0]);
        UNPACK2(l1, h1, acc[i][1]);
        float4 v = make_float4(__uint_as_float(l0) + bv.x, __uint_as_float(h0) + bv.y,
                               __uint_as_float(l1) + bv.z, __uint_as_float(h1) + bv.w);
        int gm = m0 + (tm << 2) + i;
        *(float4*)(C + (size_t)gm * ldc + c0 + (tn << 2)) = v;
    }
}

// ---------------- P6 body: cell2 gates (flag-gated) + write outs[:,t,:] ----------------
__device__ __forceinline__ void do_p6(int b, int t, float s_flag,
                                      float* __restrict__ out, float* __restrict__ out_flags) {
    const int tid = threadIdx.x;
    const bool upd = s_flag > 0.5f;
    const int j = tid << 2;
    const size_t o = (size_t)b * H_ + j;
    float4 h2v = *(const float4*)&g_h2[o];   // same-block r/w across steps: L1 valid
    if (upd) {
        const size_t z = (size_t)b * H4_ + j;
        float4 zi = cg4(&g_z2[z]);            float4 pi0 = cg4(&g_z2p0[z]);            float4 pi1 = cg4(&g_z2p1[z]);
        float4 zf = cg4(&g_z2[z + H_]);       float4 pf0 = cg4(&g_z2p0[z + H_]);       float4 pf1 = cg4(&g_z2p1[z + H_]);
        float4 zg = cg4(&g_z2[z + 2 * H_]);   float4 pg0 = cg4(&g_z2p0[z + 2 * H_]);   float4 pg1 = cg4(&g_z2p1[z + 2 * H_]);
        float4 zo = cg4(&g_z2[z + 3 * H_]);   float4 po0 = cg4(&g_z2p0[z + 3 * H_]);   float4 po1 = cg4(&g_z2p1[z + 3 * H_]);
        float4 c2v = *(const float4*)&g_c2[o];
        float xi[4] = {zi.x + pi0.x + pi1.x, zi.y + pi0.y + pi1.y, zi.z + pi0.z + pi1.z, zi.w + pi0.w + pi1.w};
        float xf[4] = {zf.x + pf0.x + pf1.x, zf.y + pf0.y + pf1.y, zf.z + pf0.z + pf1.z, zf.w + pf0.w + pf1.w};
        float xg[4] = {zg.x + pg0.x + pg1.x, zg.y + pg0.y + pg1.y, zg.z + pg0.z + pg1.z, zg.w + pg0.w + pg1.w};
        float xo[4] = {zo.x + po0.x + po1.x, zo.y + po0.y + po1.y, zo.z + po0.z + po1.z, zo.w + po0.w + po1.w};
        float cv[4] = {c2v.x, c2v.y, c2v.z, c2v.w};
        float hn[4], cn[4];
#pragma unroll
        for (int q = 0; q < 4; q++) {
            cn[q] = sigf(xf[q]) * cv[q] + sigf(xi[q]) * tanhf(xg[q]);
            hn[q] = sigf(xo[q]) * tanhf(cn[q]);
        }
        h2v = make_float4(hn[0], hn[1], hn[2], hn[3]);
        *(float4*)&g_h2[o] = h2v;
        *(float4*)&g_c2[o] = make_float4(cn[0], cn[1], cn[2], cn[3]);
    }
    *(float4*)&out[(size_t)b * S_ * H_ + (size_t)t * H_ + j] = h2v;
    if (b == 0 && tid == 0 && out_flags) out_flags[t] = s_flag;
}

// ---------------- the single persistent kernel ----------------
__global__ __launch_bounds__(NTHR, 2) void enc_kernel(
    const int* __restrict__ enc, const int* __restrict__ encx,
    const float* __restrict__ we, const float* __restrict__ ee,
    const float* __restrict__ Wsi, const float* __restrict__ Wsh,
    const float* __restrict__ b_bd, const float* __restrict__ vs,
    const float* __restrict__ Wmx1, const float* __restrict__ Wmh1,
    const float* __restrict__ Wih1, const float* __restrict__ Whh1, const float* __restrict__ b1,
    const float* __restrict__ Wmx2, const float* __restrict__ Wmh2,
    const float* __restrict__ Wih2, const float* __restrict__ Whh2, const float* __restrict__ b2,
    float* __restrict__ out, float* __restrict__ out_h2,
    float* __restrict__ out_c2, float* __restrict__ out_flags) {
    __shared__ float AsS[2][16][128];
    __shared__ float WsS[2][16][64];
    __shared__ float red[NTHR];
    __shared__ int sw[128], se[128];
    SmA* As = (SmA*)AsS;
    SmW* Ws = (SmW*)WsS;
    Sm64* A64 = (Sm64*)AsS;   // alias: first 2x(16x64) of AsS
    Sm64* W64 = (Sm64*)WsS;
    const int tid = threadIdx.x;
    const int bid = blockIdx.x;
    unsigned gen = *((volatile unsigned*)&g_bar_gen);  // persists across graph replays

    // init: zero recurrent state AND the h-side scratch for t=0 (h1=0 -> zbb=0, mh=0)
    for (int i = bid * NTHR + tid; i < B_ * H_; i += NBLK * NTHR) {
        g_h1[i] = 0.f; g_c1[i] = 0.f; g_h2[i] = 0.f; g_c2[i] = 0.f; g_mh[i] = 0.f;
    }
    for (int i = bid * NTHR + tid; i < B_ * MID_; i += NBLK * NTHR) g_zbb[i] = 0.f;

    // ---- PRECOMPUTE: all x-side GEMMs for every step (no recurrent dependency).
    for (int task = bid; task < S_ * 88; task += NBLK) {
        const int t  = task / 88;
        const int ct = task - t * 88;
        if (tid < 128) {
            sw[tid] = enc[(size_t)tid * S_ + t];
            se[tid] = encx[(size_t)tid * S_ + t];
        }
        __syncthreads();
        u64 acc[4][4] = {};
        EmbLoader el{we, ee, sw, se};
        if (ct < 8) {
            const int c0 = ct << 6;
            gemm_seg(acc, el, Wsi + (size_t)c0 * FEAT_, FEAT_, As, Ws);
            store_tile(g_zba_all + (size_t)t * B_ * MID_, MID_, c0, acc, b_bd + c0);
        } else if (ct < 24) {
            const int c0 = (ct - 8) << 6;
            gemm_seg(acc, el, Wmx1 + (size_t)c0 * FEAT_, FEAT_, As, Ws);
            store_tile(g_mx_all + (size_t)t * B_ * H_, H_, c0, acc, nullptr);
        } else {
            const int c0 = (ct - 24) << 6;
            gemm_seg(acc, el, Wih1 + (size_t)c0 * FEAT_, FEAT_, As, Ws);
            store_tile(g_z1_all + (size_t)t * B_ * H4_, H4_, c0, acc, b1 + c0);
        }
    }
    grid_barrier(gen);

    float s_prev = 0.f;   // flag of step t-1 (uniform across blocks)

    for (int t = 0; t < S_; t++) {
        // ---- PHASE_BC: P2(t) || P5(t-1).
        if (t > 0 && s_prev > 0.5f) {
            // flagged: P2 128-row tiles on 0..127; P5 128-row tiles on 168..295.
            if (bid < 128) {
                const int r = bid;
                const int c0 = (r >> 1) << 6;
                const int koff = (r & 1) << 9;
                u64 acc[4][4] = {};
                MulLoader ml{g_mx_all + (size_t)t * B_ * H_ + koff, g_mh + koff};
                gemm_seg(acc, ml, Whh1 + (size_t)c0 * H_ + koff, 512, As, Ws);
                store_tile((r & 1) ? g_z1p1 : g_z1p0, H4_, c0, acc, nullptr);
            } else if (bid >= 168) {
                const int r = bid - 168;
                const int c0 = (r >> 1) << 6;
                const int koff = (r & 1) << 9;
                u64 acc[4][4] = {};
                MulLoader ml{g_mx2 + koff, g_mh2 + koff};
                gemm_seg(acc, ml, Whh2 + (size_t)c0 * H_ + koff, 512, As, Ws);
                store_tile((r & 1) ? g_z2p1 : g_z2p0, H4_, c0, acc, nullptr);
            }
        } else {
            // unflagged: no P5 -> run P2 as paired 64-row halves, 2 CTAs on the same SM
            // (blocks b and b+148 share LUT[b%148]).
            int r = -1, m0 = 0;
            if (bid < 128) { r = bid; m0 = 0; }
            else if (bid >= 148 && bid < 276) { r = bid - 148; m0 = 64; }
            if (r >= 0) {
                const int c0 = (r >> 1) << 6;
                const int koff = (r & 1) << 9;
                u64 acc[4][2] = {};
                MulLoader ml{g_mx_all + (size_t)t * B_ * H_ + (size_t)m0 * H_ + koff,
                             g_mh + (size_t)m0 * H_ + koff};
                gemm64(acc, ml, Whh1 + (size_t)c0 * H_ + koff, 512, A64, W64);
                store_tile64((r & 1) ? g_z1p1 : g_z1p0, H4_, m0, c0, acc, nullptr);
            }
        }
        grid_barrier(gen);

        // ---- PHASE_CD: P3(t) on blocks 0..127 || P6(t-1) on blocks 168..295.
        if (bid < B_) {
            const int b = bid;
            const float* zba = g_zba_all + (size_t)t * B_ * MID_;
            float v = (cg1(&zba[(size_t)b * MID_ + tid]) + cg1(&g_zbb[(size_t)b * MID_ + tid])) * vs[tid] +
                      (cg1(&zba[(size_t)b * MID_ + 256 + tid]) + cg1(&g_zbb[(size_t)b * MID_ + 256 + tid])) * vs[256 + tid];
            red[tid] = v;
            __syncthreads();
            for (int off = 128; off > 0; off >>= 1) {
                if (tid < off) red[tid] += red[tid + off];
                __syncthreads();
            }
            const float s = (red[0] > 0.f) ? 1.f : 0.f;  // sigmoid(x)>0.5 <=> x>0 (exact)
            if (tid == 0) g_s[b] = s;
            {
                const int j = tid << 2;   // 256 threads x float4 == H_
                const size_t o = (size_t)b * H_ + j;
                const float* z1 = g_z1_all + (size_t)t * B_ * H4_;
                const size_t z = (size_t)b * H4_ + j;
                float4 zi = cg4(&z1[z]);            float4 pi0 = cg4(&g_z1p0[z]);            float4 pi1 = cg4(&g_z1p1[z]);
                float4 zf = cg4(&z1[z + H_]);       float4 pf0 = cg4(&g_z1p0[z + H_]);       float4 pf1 = cg4(&g_z1p1[z + H_]);
                float4 zg = cg4(&z1[z + 2 * H_]);   float4 pg0 = cg4(&g_z1p0[z + 2 * H_]);   float4 pg1 = cg4(&g_z1p1[z + 2 * H_]);
                float4 zo = cg4(&z1[z + 3 * H_]);   float4 po0 = cg4(&g_z1p0[z + 3 * H_]);   float4 po1 = cg4(&g_z1p1[z + 3 * H_]);
                float4 c1v = *(const float4*)&g_c1[o];   // same-block r/w across steps: L1 valid
                float xi[4] = {zi.x + pi0.x + pi1.x, zi.y + pi0.y + pi1.y, zi.z + pi0.z + pi1.z, zi.w + pi0.w + pi1.w};
                float xf[4] = {zf.x + pf0.x + pf1.x, zf.y + pf0.y + pf1.y, zf.z + pf0.z + pf1.z, zf.w + pf0.w + pf1.w};
                float xg[4] = {zg.x + pg0.x + pg1.x, zg.y + pg0.y + pg1.y, zg.z + pg0.z + pg1.z, zg.w + pg0.w + pg1.w};
                float xo[4] = {zo.x + po0.x + po1.x, zo.y + po0.y + po1.y, zo.z + po0.z + po1.z, zo.w + po0.w + po1.w};
                float cv[4] = {c1v.x, c1v.y, c1v.z, c1v.w};
                float x2v[4], h1v[4], c1n[4];
#pragma unroll
                for (int q = 0; q < 4; q++) {
                    float cn = sigf(xf[q]) * cv[q] + sigf(xi[q]) * tanhf(xg[q]);
                    float hn = sigf(xo[q]) * tanhf(cn);
                    x2v[q] = hn * s;
                    h1v[q] = hn * (1.f - s);
                    c1n[q] = cn * (1.f - s);
                }
                *(float4*)&g_x2[o] = make_float4(x2v[0], x2v[1], x2v[2], x2v[3]);
                *(float4*)&g_h1[o] = make_float4(h1v[0], h1v[1], h1v[2], h1v[3]);
                *(float4*)&g_c1[o] = make_float4(c1n[0], c1n[1], c1n[2], c1n[3]);
            }
        } else if (bid >= 168 && t > 0) {
            do_p6(bid - 168, t - 1, s_prev, out, out_flags);
        }
        grid_barrier(gen);

        const float s_cur = cg1(&g_s[0]);  // uniform after barrier -> uniform control flow

        // ---- PHASE_A: paired 64-row halves on the same SM (b and b+148).
        //      P4(t) when flag: ct 0..95 -> blocks {ct, ct+148}.
        //      P1'(t+1) always:  p 0..23 -> blocks {96+p, 244+p}.
        {
            int ct = -1, m0 = 0;
            if (bid < 96) { ct = bid; m0 = 0; }
            else if (bid >= 148 && bid < 244) { ct = bid - 148; m0 = 64; }
            if (s_cur > 0.5f && ct >= 0) {
                u64 acc[4][2] = {};
                if (ct < 16) {
                    const int c0 = ct << 6;
                    BufLoader bl{g_x2 + (size_t)m0 * H_, H_};
                    gemm64(acc, bl, Wmx2 + (size_t)c0 * H_, H_, A64, W64);
                    store_tile64(g_mx2, H_, m0, c0, acc, nullptr);
                } else if (ct < 32) {
                    const int c0 = (ct - 16) << 6;
                    BufLoader bl{g_h2 + (size_t)m0 * H_, H_};
                    gemm64(acc, bl, Wmh2 + (size_t)c0 * H_, H_, A64, W64);
                    store_tile64(g_mh2, H_, m0, c0, acc, nullptr);
                } else {
                    const int c0 = (ct - 32) << 6;
                    BufLoader bl{g_x2 + (size_t)m0 * H_, H_};
                    gemm64(acc, bl, Wih2 + (size_t)c0 * H_, H_, A64, W64);
                    store_tile64(g_z2, H4_, m0, c0, acc, b2 + c0);
                }
            }
            int p = -1; m0 = 0;
            if (bid >= 96 && bid < 120) { p = bid - 96; m0 = 0; }
            else if (bid >= 244 && bid < 268) { p = bid - 244; m0 = 64; }
            if (p >= 0) {
                u64 acc[4][2] = {};
                BufLoader bl{g_h1 + (size_t)m0 * H_, H_};
                if (p < 8) {
                    const int c0 = p << 6;
                    gemm64(acc, bl, Wsh + (size_t)c0 * H_, H_, A64, W64);
                    store_tile64(g_zbb, MID_, m0, c0, acc, nullptr);
                } else {
                    const int c0 = (p - 8) << 6;
                    gemm64(acc, bl, Wmh1 + (size_t)c0 * H_, H_, A64, W64);
                    store_tile64(g_mh, H_, m0, c0, acc, nullptr);
                }
            }
        }
        grid_barrier(gen);

        s_prev = s_cur;
    }

    // ---- epilogue: P5(S-1) if flagged, then P6(S-1), then final state copy.
    if (s_prev > 0.5f) {
        if (bid < 128) {
            const int r = bid;
            const int c0 = (r >> 1) << 6;
            const int koff = (r & 1) << 9;
            u64 acc[4][4] = {};
            MulLoader ml{g_mx2 + koff, g_mh2 + koff};
            gemm_seg(acc, ml, Whh2 + (size_t)c0 * H_ + koff, 512, As, Ws);
            store_tile((r & 1) ? g_z2p1 : g_z2p0, H4_, c0, acc, nullptr);
        }
        grid_barrier(gen);
    }
    if (bid >= 168) {
        do_p6(bid - 168, S_ - 1, s_prev, out, out_flags);
    }
    grid_barrier(gen);
    if (out_h2) {
        for (int i = bid * NTHR + tid; i < B_ * H_; i += NBLK * NTHR) {
            out_h2[i] = cg1(&g_h2[i]);
            out_c2[i] = cg1(&g_c2[i]);
        }
    }
}

// ---------------- host: exactly ONE graph node ----------------
extern "C" void kernel_launch(void* const* d_in, const int* in_sizes, int n_in,
                              void* d_out, int out_size) {
    const int*   enc   = (const int*)d_in[0];
    const int*   encx  = (const int*)d_in[1];
    const float* we    = (const float*)d_in[2];
    const float* ee    = (const float*)d_in[3];
    const float* Wsi   = (const float*)d_in[4];
    const float* Wsh   = (const float*)d_in[5];
    const float* b_bd  = (const float*)d_in[6];
    const float* vs    = (const float*)d_in[7];
    const float* Wmx1  = (const float*)d_in[8];
    const float* Wmh1  = (const float*)d_in[9];
    const float* Wih1  = (const float*)d_in[10];
    const float* Whh1  = (const float*)d_in[11];
    const float* b1    = (const float*)d_in[12];
    const float* Wmx2  = (const float*)d_in[13];
    const float* Wmh2  = (const float*)d_in[14];
    const float* Wih2  = (const float*)d_in[15];
    const float* Whh2  = (const float*)d_in[16];
    const float* b2    = (const float*)d_in[17];
    float* out = (float*)d_out;

    const size_t outs_elems  = (size_t)B_ * S_ * H_;
    const size_t state_elems = (size_t)B_ * H_;
    float* out_h2 = nullptr;
    float* out_c2 = nullptr;
    float* out_flags = nullptr;
    if ((size_t)out_size >= outs_elems + 2 * state_elems + S_) {
        out_h2 = out + outs_elems;
        out_c2 = out_h2 + state_elems;
        out_flags = out_c2 + state_elems;
    }

    enc_kernel<<<NBLK, NTHR>>>(enc, encx, we, ee, Wsi, Wsh, b_bd, vs,
                               Wmx1, Wmh1, Wih1, Whh1, b1,
                               Wmx2, Wmh2, Wih2, Whh2, b2,
                               out, out_h2, out_c2, out_flags);
    (void)in_sizes; (void)n_in;
}

// round 15
// speedup vs baseline: 1.0534x; 1.0534x over previous
#include <cuda_runtime.h>
#include <cstdint>

#define B_    128
#define S_    512
#define H_    1024
#define MID_  512
#define E_    512
#define XE_   64
#define FEAT_ 576
#define H4_   4096
#define NBLK  296
#define NTHR  256

typedef unsigned long long u64;

// ---------------- persistent state + scratch (device globals; no allocs) ----------------
__device__ float g_h1[B_ * H_];
__device__ float g_c1[B_ * H_];
__device__ float g_h2[B_ * H_];
__device__ float g_c2[B_ * H_];
__device__ float g_zbb[B_ * MID_];    // h-side boundary partial, k-half 0
__device__ float g_zbbB[B_ * MID_];   // k-half 1
__device__ float g_mh[B_ * H_];       // mh partial, k-half 0
__device__ float g_mhB[B_ * H_];      // k-half 1
__device__ float g_z1p0[B_ * H4_];
__device__ float g_z1p1[B_ * H4_];
__device__ float g_x2[B_ * H_];
__device__ float g_mx2[B_ * H_];      // k-half 0
__device__ float g_mx2B[B_ * H_];     // k-half 1
__device__ float g_mh2[B_ * H_];
__device__ float g_mh2B[B_ * H_];
__device__ float g_z2[B_ * H4_];      // k-half 0 (+bias)
__device__ float g_z2B[B_ * H4_];     // k-half 1
__device__ float g_z2p0[B_ * H4_];
__device__ float g_z2p1[B_ * H4_];
__device__ float g_s[B_];
__device__ unsigned g_bar_count = 0;
__device__ unsigned g_bar_gen = 0;
// precomputed x-side results for ALL steps (input-only dependent)
__device__ float g_zba_all[S_ * B_ * MID_];
__device__ float g_mx_all[S_ * B_ * H_];
__device__ float g_z1_all[S_ * B_ * H4_];

__device__ __forceinline__ float sigf(float x) { return 1.f / (1.f + expf(-x)); }
__device__ __forceinline__ float4 cg4(const float* p) { return __ldcg((const float4*)p); }
__device__ __forceinline__ float  cg1(const float* p) { return __ldcg(p); }

#define FMA2(acc, a, b) asm("fma.rn.f32x2 %0, %1, %2, %0;" : "+l"(acc) : "l"(a), "l"(b))
#define PACK2(d, f)     asm("mov.b64 %0, {%1, %1};" : "=l"(d) : "r"(__float_as_uint(f)))
#define UNPACK2(lo, hi, v) asm("mov.b64 {%0, %1}, %2;" : "=r"(lo), "=r"(hi) : "l"(v))

// ---------------- grid-wide barrier (all NBLK blocks co-resident: 2 CTAs x 148 SMs) ----------------
__device__ __forceinline__ void grid_barrier(unsigned& gen) {
    __syncthreads();
    if (threadIdx.x == 0) {
        __threadfence();
        unsigned arrived = atomicAdd(&g_bar_count, 1u) + 1u;
        if (arrived == (unsigned)NBLK) {
            g_bar_count = 0;
            __threadfence();
            atomicExch(&g_bar_gen, gen + 1u);
        } else {
            unsigned cur;
            do {
                __nanosleep(64);
                asm volatile("ld.global.cg.u32 %0, [%1];" : "=r"(cur) : "l"(&g_bar_gen));
            } while (cur == gen);
        }
        __threadfence();
    }
    __syncthreads();
    gen++;
}

// ---------------- A-tile loaders (M = 128 = full batch; pre-offset by koff where used) ----------------
struct BufLoader {
    const float* A; int lda;
    __device__ __forceinline__ float4 ld(int m, int k) const {
        return cg4(A + (size_t)m * lda + k);
    }
};
struct Mul2Loader {  // A[m][k] = X[m][k] * (Y0[m][k] + Y1[m][k])
    const float* X; const float* Y0; const float* Y1;
    __device__ __forceinline__ float4 ld(int m, int k) const {
        float4 a  = cg4(X  + (size_t)m * H_ + k);
        float4 b0 = cg4(Y0 + (size_t)m * H_ + k);
        float4 b1 = cg4(Y1 + (size_t)m * H_ + k);
        return make_float4(a.x * (b0.x + b1.x), a.y * (b0.y + b1.y),
                           a.z * (b0.z + b1.z), a.w * (b0.w + b1.w));
    }
};
struct Mul4Loader {  // A[m][k] = (X0+X1)[m][k] * (Y0+Y1)[m][k]
    const float* X0; const float* X1; const float* Y0; const float* Y1;
    __device__ __forceinline__ float4 ld(int m, int k) const {
        float4 a0 = cg4(X0 + (size_t)m * H_ + k);
        float4 a1 = cg4(X1 + (size_t)m * H_ + k);
        float4 b0 = cg4(Y0 + (size_t)m * H_ + k);
        float4 b1 = cg4(Y1 + (size_t)m * H_ + k);
        return make_float4((a0.x + a1.x) * (b0.x + b1.x), (a0.y + a1.y) * (b0.y + b1.y),
                           (a0.z + a1.z) * (b0.z + b1.z), (a0.w + a1.w) * (b0.w + b1.w));
    }
};
struct EmbLoader {
    const float* we; const float* ee; const int* sw; const int* se;
    __device__ __forceinline__ float4 ld(int m, int k) const {
        if (k < E_) return *(const float4*)(we + (size_t)sw[m] * E_ + k);
        return *(const float4*)(ee + (size_t)se[m] * XE_ + (k - E_));
    }
};

typedef float SmA[16][128];
typedef float SmW[16][64];

// ---------------- 128x64 tile GEMM: acc += A[128,K] @ Wtile[64,K]^T ----------------
// R8 inner loop (proven best). lda = W row stride (SEPARATE from k-extent K —
// split-K tiles have lda=H_ > K. Using K as stride was the R5..R13 latent bug).
template <class AL>
__device__ __forceinline__ void gemm_seg(u64 (&acc)[4][4], const AL& al,
                                         const float* __restrict__ W, int K, int lda,
                                         SmA* As, SmW* Ws) {
    const int tid = threadIdx.x;
    const int lm  = tid >> 2;
    const int lk  = (tid & 3) << 2;
    const int tm  = tid >> 4;
    const int tn  = tid & 15;
    float4 a0 = al.ld(lm, lk);
    float4 a1 = al.ld(lm + 64, lk);
    float4 w  = *(const float4*)(W + (size_t)lm * lda + lk);
    const int nch = K >> 4;
    int buf = 0;
    for (int ch = 0; ch < nch; ch++) {
        As[buf][lk + 0][lm] = a0.x; As[buf][lk + 1][lm] = a0.y;
        As[buf][lk + 2][lm] = a0.z; As[buf][lk + 3][lm] = a0.w;
        As[buf][lk + 0][lm + 64] = a1.x; As[buf][lk + 1][lm + 64] = a1.y;
        As[buf][lk + 2][lm + 64] = a1.z; As[buf][lk + 3][lm + 64] = a1.w;
        Ws[buf][lk + 0][lm] = w.x; Ws[buf][lk + 1][lm] = w.y;
        Ws[buf][lk + 2][lm] = w.z; Ws[buf][lk + 3][lm] = w.w;
        __syncthreads();
        if (ch + 1 < nch) {
            a0 = al.ld(lm, ((ch + 1) << 4) + lk);
            a1 = al.ld(lm + 64, ((ch + 1) << 4) + lk);
            w  = *(const float4*)(W + (size_t)lm * lda + ((ch + 1) << 4) + lk);
        }
#pragma unroll
        for (int kk = 0; kk < 16; kk++) {
            ulonglong2 ar0 = *(const ulonglong2*)&As[buf][kk][tm << 3];
            ulonglong2 ar1 = *(const ulonglong2*)&As[buf][kk][(tm << 3) + 4];
            float4 wv = *(const float4*)&Ws[buf][kk][tn << 2];
            u64 wp;
            PACK2(wp, wv.x);
            FMA2(acc[0][0], ar0.x, wp); FMA2(acc[0][1], ar0.y, wp);
            FMA2(acc[0][2], ar1.x, wp); FMA2(acc[0][3], ar1.y, wp);
            PACK2(wp, wv.y);
            FMA2(acc[1][0], ar0.x, wp); FMA2(acc[1][1], ar0.y, wp);
            FMA2(acc[1][2], ar1.x, wp); FMA2(acc[1][3], ar1.y, wp);
            PACK2(wp, wv.z);
            FMA2(acc[2][0], ar0.x, wp); FMA2(acc[2][1], ar0.y, wp);
            FMA2(acc[2][2], ar1.x, wp); FMA2(acc[2][3], ar1.y, wp);
            PACK2(wp, wv.w);
            FMA2(acc[3][0], ar0.x, wp); FMA2(acc[3][1], ar0.y, wp);
            FMA2(acc[3][2], ar1.x, wp); FMA2(acc[3][3], ar1.y, wp);
        }
        buf ^= 1;
    }
    __syncthreads();
}

__device__ __forceinline__ void store_tile(float* __restrict__ C, int ldc, int c0,
                                           u64 (&acc)[4][4], const float* __restrict__ bias) {
    const int tid = threadIdx.x;
    const int tm = tid >> 4, tn = tid & 15;
    float4 bv = make_float4(0.f, 0.f, 0.f, 0.f);
    if (bias) bv = *(const float4*)(bias + (tn << 2));
#pragma unroll
    for (int rp = 0; rp < 4; rp++) {
        unsigned l0, h0, l1, h1, l2, h2, l3, h3;
        UNPACK2(l0, h0, acc[0][rp]);
        UNPACK2(l1, h1, acc[1][rp]);
        UNPACK2(l2, h2, acc[2][rp]);
        UNPACK2(l3, h3, acc[3][rp]);
        const int r0 = (tm << 3) + (rp << 1);
        *(float4*)(C + (size_t)r0 * ldc + c0 + (tn << 2)) =
            make_float4(__uint_as_float(l0) + bv.x, __uint_as_float(l1) + bv.y,
                        __uint_as_float(l2) + bv.z, __uint_as_float(l3) + bv.w);
        *(float4*)(C + (size_t)(r0 + 1) * ldc + c0 + (tn << 2)) =
            make_float4(__uint_as_float(h0) + bv.x, __uint_as_float(h1) + bv.y,
                        __uint_as_float(h2) + bv.z, __uint_as_float(h3) + bv.w);
    }
}

// ---------------- P6 body: cell2 gates (flag-gated) + write outs[:,t,:] ----------------
__device__ __forceinline__ void do_p6(int b, int t, float s_flag,
                                      float* __restrict__ out, float* __restrict__ out_flags) {
    const int tid = threadIdx.x;
    const bool upd = s_flag > 0.5f;
    const int j = tid << 2;
    const size_t o = (size_t)b * H_ + j;
    float4 h2v = *(const float4*)&g_h2[o];
    if (upd) {
        const size_t z = (size_t)b * H4_ + j;
        float4 zi = cg4(&g_z2[z]);             float4 ziB = cg4(&g_z2B[z]);
        float4 pi0 = cg4(&g_z2p0[z]);          float4 pi1 = cg4(&g_z2p1[z]);
        float4 zf = cg4(&g_z2[z + H_]);        float4 zfB = cg4(&g_z2B[z + H_]);
        float4 pf0 = cg4(&g_z2p0[z + H_]);     float4 pf1 = cg4(&g_z2p1[z + H_]);
        float4 zg = cg4(&g_z2[z + 2 * H_]);    float4 zgB = cg4(&g_z2B[z + 2 * H_]);
        float4 pg0 = cg4(&g_z2p0[z + 2 * H_]); float4 pg1 = cg4(&g_z2p1[z + 2 * H_]);
        float4 zo = cg4(&g_z2[z + 3 * H_]);    float4 zoB = cg4(&g_z2B[z + 3 * H_]);
        float4 po0 = cg4(&g_z2p0[z + 3 * H_]); float4 po1 = cg4(&g_z2p1[z + 3 * H_]);
        float4 c2v = *(const float4*)&g_c2[o];
        float xi[4] = {zi.x + ziB.x + pi0.x + pi1.x, zi.y + ziB.y + pi0.y + pi1.y,
                       zi.z + ziB.z + pi0.z + pi1.z, zi.w + ziB.w + pi0.w + pi1.w};
        float xf[4] = {zf.x + zfB.x + pf0.x + pf1.x, zf.y + zfB.y + pf0.y + pf1.y,
                       zf.z + zfB.z + pf0.z + pf1.z, zf.w + zfB.w + pf0.w + pf1.w};
        float xg[4] = {zg.x + zgB.x + pg0.x + pg1.x, zg.y + zgB.y + pg0.y + pg1.y,
                       zg.z + zgB.z + pg0.z + pg1.z, zg.w + zgB.w + pg0.w + pg1.w};
        float xo[4] = {zo.x + zoB.x + po0.x + po1.x, zo.y + zoB.y + po0.y + po1.y,
                       zo.z + zoB.z + po0.z + po1.z, zo.w + zoB.w + po0.w + po1.w};
        float cv[4] = {c2v.x, c2v.y, c2v.z, c2v.w};
        float hn[4], cn[4];
#pragma unroll
        for (int q = 0; q < 4; q++) {
            cn[q] = sigf(xf[q]) * cv[q] + sigf(xi[q]) * tanhf(xg[q]);
            hn[q] = sigf(xo[q]) * tanhf(cn[q]);
        }
        h2v = make_float4(hn[0], hn[1], hn[2], hn[3]);
        *(float4*)&g_h2[o] = h2v;
        *(float4*)&g_c2[o] = make_float4(cn[0], cn[1], cn[2], cn[3]);
    }
    *(float4*)&out[(size_t)b * S_ * H_ + (size_t)t * H_ + j] = h2v;
    if (b == 0 && tid == 0 && out_flags) out_flags[t] = s_flag;
}

// ---------------- the single persistent kernel ----------------
__global__ __launch_bounds__(NTHR, 2) void enc_kernel(
    const int* __restrict__ enc, const int* __restrict__ encx,
    const float* __restrict__ we, const float* __restrict__ ee,
    const float* __restrict__ Wsi, const float* __restrict__ Wsh,
    const float* __restrict__ b_bd, const float* __restrict__ vs,
    const float* __restrict__ Wmx1, const float* __restrict__ Wmh1,
    const float* __restrict__ Wih1, const float* __restrict__ Whh1, const float* __restrict__ b1,
    const float* __restrict__ Wmx2, const float* __restrict__ Wmh2,
    const float* __restrict__ Wih2, const float* __restrict__ Whh2, const float* __restrict__ b2,
    float* __restrict__ out, float* __restrict__ out_h2,
    float* __restrict__ out_c2, float* __restrict__ out_flags) {
    __shared__ float As[2][16][128];
    __shared__ float Ws[2][16][64];
    __shared__ float red[NTHR];
    __shared__ int sw[128], se[128];
    const int tid = threadIdx.x;
    const int bid = blockIdx.x;
    unsigned gen = *((volatile unsigned*)&g_bar_gen);

    // init: zero recurrent state AND the h-side partials for t=0
    for (int i = bid * NTHR + tid; i < B_ * H_; i += NBLK * NTHR) {
        g_h1[i] = 0.f; g_c1[i] = 0.f; g_h2[i] = 0.f; g_c2[i] = 0.f;
        g_mh[i] = 0.f; g_mhB[i] = 0.f;
    }
    for (int i = bid * NTHR + tid; i < B_ * MID_; i += NBLK * NTHR) {
        g_zbb[i] = 0.f; g_zbbB[i] = 0.f;
    }

    // ---- PRECOMPUTE: all x-side GEMMs for every step (no recurrent dependency).
    for (int task = bid; task < S_ * 88; task += NBLK) {
        const int t  = task / 88;
        const int ct = task - t * 88;
        if (tid < 128) {
            sw[tid] = enc[(size_t)tid * S_ + t];
            se[tid] = encx[(size_t)tid * S_ + t];
        }
        __syncthreads();
        u64 acc[4][4] = {};
        EmbLoader el{we, ee, sw, se};
        if (ct < 8) {
            const int c0 = ct << 6;
            gemm_seg(acc, el, Wsi + (size_t)c0 * FEAT_, FEAT_, FEAT_, As, Ws);
            store_tile(g_zba_all + (size_t)t * B_ * MID_, MID_, c0, acc, b_bd + c0);
        } else if (ct < 24) {
            const int c0 = (ct - 8) << 6;
            gemm_seg(acc, el, Wmx1 + (size_t)c0 * FEAT_, FEAT_, FEAT_, As, Ws);
            store_tile(g_mx_all + (size_t)t * B_ * H_, H_, c0, acc, nullptr);
        } else {
            const int c0 = (ct - 24) << 6;
            gemm_seg(acc, el, Wih1 + (size_t)c0 * FEAT_, FEAT_, FEAT_, As, Ws);
            store_tile(g_z1_all + (size_t)t * B_ * H4_, H4_, c0, acc, b1 + c0);
        }
    }
    grid_barrier(gen);

    float s_prev = 0.f;

    for (int t = 0; t < S_; t++) {
        // ---- PHASE_BC: P2(t) on 0..127 || P5(t-1) on 168..295 (if prev flag).
        if (bid < 128) {
            const int r = bid;
            const int c0 = (r >> 1) << 6;
            const int koff = (r & 1) << 9;
            u64 acc[4][4] = {};
            Mul2Loader ml{g_mx_all + (size_t)t * B_ * H_ + koff, g_mh + koff, g_mhB + koff};
            gemm_seg(acc, ml, Whh1 + (size_t)c0 * H_ + koff, 512, H_, As, Ws);
            store_tile((r & 1) ? g_z1p1 : g_z1p0, H4_, c0, acc, nullptr);
        } else if (bid >= 168 && t > 0 && s_prev > 0.5f) {
            const int r = bid - 168;
            const int c0 = (r >> 1) << 6;
            const int koff = (r & 1) << 9;
            u64 acc[4][4] = {};
            Mul4Loader ml{g_mx2 + koff, g_mx2B + koff, g_mh2 + koff, g_mh2B + koff};
            gemm_seg(acc, ml, Whh2 + (size_t)c0 * H_ + koff, 512, H_, As, Ws);
            store_tile((r & 1) ? g_z2p1 : g_z2p0, H4_, c0, acc, nullptr);
        }
        grid_barrier(gen);

        // ---- PHASE_CD: P3(t) on 0..127 || P6(t-1) on 168..295.
        if (bid < B_) {
            const int b = bid;
            const float* zba = g_zba_all + (size_t)t * B_ * MID_;
            float v = (cg1(&zba[(size_t)b * MID_ + tid]) + cg1(&g_zbb[(size_t)b * MID_ + tid]) +
                       cg1(&g_zbbB[(size_t)b * MID_ + tid])) * vs[tid] +
                      (cg1(&zba[(size_t)b * MID_ + 256 + tid]) + cg1(&g_zbb[(size_t)b * MID_ + 256 + tid]) +
                       cg1(&g_zbbB[(size_t)b * MID_ + 256 + tid])) * vs[256 + tid];
            red[tid] = v;
            __syncthreads();
            for (int off = 128; off > 0; off >>= 1) {
                if (tid < off) red[tid] += red[tid + off];
                __syncthreads();
            }
            const float s = (red[0] > 0.f) ? 1.f : 0.f;
            if (tid == 0) g_s[b] = s;
            {
                const int j = tid << 2;
                const size_t o = (size_t)b * H_ + j;
                const float* z1 = g_z1_all + (size_t)t * B_ * H4_;
                const size_t z = (size_t)b * H4_ + j;
                float4 zi = cg4(&z1[z]);            float4 pi0 = cg4(&g_z1p0[z]);            float4 pi1 = cg4(&g_z1p1[z]);
                float4 zf = cg4(&z1[z + H_]);       float4 pf0 = cg4(&g_z1p0[z + H_]);       float4 pf1 = cg4(&g_z1p1[z + H_]);
                float4 zg = cg4(&z1[z + 2 * H_]);   float4 pg0 = cg4(&g_z1p0[z + 2 * H_]);   float4 pg1 = cg4(&g_z1p1[z + 2 * H_]);
                float4 zo = cg4(&z1[z + 3 * H_]);   float4 po0 = cg4(&g_z1p0[z + 3 * H_]);   float4 po1 = cg4(&g_z1p1[z + 3 * H_]);
                float4 c1v = *(const float4*)&g_c1[o];
                float xi[4] = {zi.x + pi0.x + pi1.x, zi.y + pi0.y + pi1.y, zi.z + pi0.z + pi1.z, zi.w + pi0.w + pi1.w};
                float xf[4] = {zf.x + pf0.x + pf1.x, zf.y + pf0.y + pf1.y, zf.z + pf0.z + pf1.z, zf.w + pf0.w + pf1.w};
                float xg[4] = {zg.x + pg0.x + pg1.x, zg.y + pg0.y + pg1.y, zg.z + pg0.z + pg1.z, zg.w + pg0.w + pg1.w};
                float xo[4] = {zo.x + po0.x + po1.x, zo.y + po0.y + po1.y, zo.z + po0.z + po1.z, zo.w + po0.w + po1.w};
                float cv[4] = {c1v.x, c1v.y, c1v.z, c1v.w};
                float x2v[4], h1v[4], c1n[4];
#pragma unroll
                for (int q = 0; q < 4; q++) {
                    float cn = sigf(xf[q]) * cv[q] + sigf(xi[q]) * tanhf(xg[q]);
                    float hn = sigf(xo[q]) * tanhf(cn);
                    x2v[q] = hn * s;
                    h1v[q] = hn * (1.f - s);
                    c1n[q] = cn * (1.f - s);
                }
                *(float4*)&g_x2[o] = make_float4(x2v[0], x2v[1], x2v[2], x2v[3]);
                *(float4*)&g_h1[o] = make_float4(h1v[0], h1v[1], h1v[2], h1v[3]);
                *(float4*)&g_c1[o] = make_float4(c1n[0], c1n[1], c1n[2], c1n[3]);
            }
        } else if (bid >= 168 && t > 0) {
            do_p6(bid - 168, t - 1, s_prev, out, out_flags);
        }
        grid_barrier(gen);

        const float s_cur = cg1(&g_s[0]);

        // ---- PHASE_A (all GEMMs K=512 halves, lda=H_):
        //      flagged: P4 split = 192 tasks on 0..191; P1' split = 48 tasks on 192..239.
        //      unflagged: P1' split = 48 tasks on 0..47.
        if (s_cur > 0.5f && bid < 192) {
            const int ct = bid % 96;
            const int kh = bid / 96;
            const int koff = kh << 9;
            u64 acc[4][4] = {};
            if (ct < 16) {
                const int c0 = ct << 6;
                BufLoader bl{g_x2 + koff, H_};
                gemm_seg(acc, bl, Wmx2 + (size_t)c0 * H_ + koff, 512, H_, As, Ws);
                store_tile(kh ? g_mx2B : g_mx2, H_, c0, acc, nullptr);
            } else if (ct < 32) {
                const int c0 = (ct - 16) << 6;
                BufLoader bl{g_h2 + koff, H_};
                gemm_seg(acc, bl, Wmh2 + (size_t)c0 * H_ + koff, 512, H_, As, Ws);
                store_tile(kh ? g_mh2B : g_mh2, H_, c0, acc, nullptr);
            } else {
                const int c0 = (ct - 32) << 6;
                BufLoader bl{g_x2 + koff, H_};
                gemm_seg(acc, bl, Wih2 + (size_t)c0 * H_ + koff, 512, H_, As, Ws);
                store_tile(kh ? g_z2B : g_z2, H4_, c0, acc, kh ? nullptr : (b2 + c0));
            }
        }
        {
            int p2 = -1;
            if (s_cur > 0.5f) { if (bid >= 192 && bid < 240) p2 = bid - 192; }
            else             { if (bid < 48) p2 = bid; }
            if (p2 >= 0) {
                const int p  = p2 % 24;
                const int kh = p2 / 24;
                const int koff = kh << 9;
                u64 acc[4][4] = {};
                BufLoader bl{g_h1 + koff, H_};
                if (p < 8) {
                    const int c0 = p << 6;
                    gemm_seg(acc, bl, Wsh + (size_t)c0 * H_ + koff, 512, H_, As, Ws);
                    store_tile(kh ? g_zbbB : g_zbb, MID_, c0, acc, nullptr);
                } else {
                    const int c0 = (p - 8) << 6;
                    gemm_seg(acc, bl, Wmh1 + (size_t)c0 * H_ + koff, 512, H_, As, Ws);
                    store_tile(kh ? g_mhB : g_mh, H_, c0, acc, nullptr);
                }
            }
        }
        grid_barrier(gen);

        s_prev = s_cur;
    }

    // ---- epilogue: P5(S-1) if flagged, then P6(S-1), then final state copy.
    if (s_prev > 0.5f) {
        if (bid < 128) {
            const int r = bid;
            const int c0 = (r >> 1) << 6;
            const int koff = (r & 1) << 9;
            u64 acc[4][4] = {};
            Mul4Loader ml{g_mx2 + koff, g_mx2B + koff, g_mh2 + koff, g_mh2B + koff};
            gemm_seg(acc, ml, Whh2 + (size_t)c0 * H_ + koff, 512, H_, As, Ws);
            store_tile((r & 1) ? g_z2p1 : g_z2p0, H4_, c0, acc, nullptr);
        }
        grid_barrier(gen);
    }
    if (bid >= 168) {
        do_p6(bid - 168, S_ - 1, s_prev, out, out_flags);
    }
    grid_barrier(gen);
    if (out_h2) {
        for (int i = bid * NTHR + tid; i < B_ * H_; i += NBLK * NTHR) {
            out_h2[i] = cg1(&g_h2[i]);
            out_c2[i] = cg1(&g_c2[i]);
        }
    }
}

// ---------------- host: exactly ONE graph node ----------------
extern "C" void kernel_launch(void* const* d_in, const int* in_sizes, int n_in,
                              void* d_out, int out_size) {
    const int*   enc   = (const int*)d_in[0];
    const int*   encx  = (const int*)d_in[1];
    const float* we    = (const float*)d_in[2];
    const float* ee    = (const float*)d_in[3];
    const float* Wsi   = (const float*)d_in[4];
    const float* Wsh   = (const float*)d_in[5];
    const float* b_bd  = (const float*)d_in[6];
    const float* vs    = (const float*)d_in[7];
    const float* Wmx1  = (const float*)d_in[8];
    const float* Wmh1  = (const float*)d_in[9];
    const float* Wih1  = (const float*)d_in[10];
    const float* Whh1  = (const float*)d_in[11];
    const float* b1    = (const float*)d_in[12];
    const float* Wmx2  = (const float*)d_in[13];
    const float* Wmh2  = (const float*)d_in[14];
    const float* Wih2  = (const float*)d_in[15];
    const float* Whh2  = (const float*)d_in[16];
    const float* b2    = (const float*)d_in[17];
    float* out = (float*)d_out;

    const size_t outs_elems  = (size_t)B_ * S_ * H_;
    const size_t state_elems = (size_t)B_ * H_;
    float* out_h2 = nullptr;
    float* out_c2 = nullptr;
    float* out_flags = nullptr;
    if ((size_t)out_size >= outs_elems + 2 * state_elems + S_) {
        out_h2 = out + outs_elems;
        out_c2 = out_h2 + state_elems;
        out_flags = out_c2 + state_elems;
    }

    enc_kernel<<<NBLK, NTHR>>>(enc, encx, we, ee, Wsi, Wsh, b_bd, vs,
                               Wmx1, Wmh1, Wih1, Whh1, b1,
                               Wmx2, Wmh2, Wih2, Whh2, b2,
                               out, out_h2, out_c2, out_flags);
    (void)in_sizes; (void)n_in;
}

// round 16
// speedup vs baseline: 1.3357x; 1.2680x over previous
#include <cuda_runtime.h>
#include <cstdint>

#define B_    128
#define S_    512
#define H_    1024
#define MID_  512
#define E_    512
#define XE_   64
#define FEAT_ 576
#define H4_   4096
#define NBLK  296
#define NTHR  256

typedef unsigned long long u64;

// ---------------- persistent state + scratch (device globals; no allocs) ----------------
__device__ float g_h1[B_ * H_];
__device__ float g_c1[B_ * H_];
__device__ float g_h2[B_ * H_];
__device__ float g_c2[B_ * H_];
__device__ float g_zbb[B_ * MID_];    // h-side boundary partial, k-half 0
__device__ float g_zbbB[B_ * MID_];   // k-half 1
__device__ float g_mh[B_ * H_];       // mh partial, k-half 0
__device__ float g_mhB[B_ * H_];      // k-half 1
__device__ float g_z1p0[B_ * H4_];
__device__ float g_z1p1[B_ * H4_];
__device__ float g_x2[B_ * H_];
__device__ float g_mx2[B_ * H_];      // k-half 0
__device__ float g_mx2B[B_ * H_];     // k-half 1
__device__ float g_mh2[B_ * H_];
__device__ float g_mh2B[B_ * H_];
__device__ float g_z2[B_ * H4_];      // k-half 0 (+bias)
__device__ float g_z2B[B_ * H4_];     // k-half 1
__device__ float g_z2p0[B_ * H4_];
__device__ float g_z2p1[B_ * H4_];
__device__ float g_s[B_];
__device__ unsigned g_bar_count = 0;
__device__ unsigned g_bar_gen = 0;
// precomputed x-side results for ALL steps (input-only dependent)
__device__ float g_zba_all[S_ * B_ * MID_];
__device__ float g_mx_all[S_ * B_ * H_];
__device__ float g_z1_all[S_ * B_ * H4_];

__device__ __forceinline__ float sigf(float x) { return 1.f / (1.f + expf(-x)); }
__device__ __forceinline__ float4 cg4(const float* p) { return __ldcg((const float4*)p); }
__device__ __forceinline__ float  cg1(const float* p) { return __ldcg(p); }

#define FMA2(acc, a, b) asm("fma.rn.f32x2 %0, %1, %2, %0;" : "+l"(acc) : "l"(a), "l"(b))
#define PACK2(d, f)     asm("mov.b64 %0, {%1, %1};" : "=l"(d) : "r"(__float_as_uint(f)))
#define UNPACK2(lo, hi, v) asm("mov.b64 {%0, %1}, %2;" : "=r"(lo), "=r"(hi) : "l"(v))

// ---------------- grid-wide barrier (all NBLK blocks co-resident: 2 CTAs x 148 SMs) ----------------
__device__ __forceinline__ void grid_barrier(unsigned& gen) {
    __syncthreads();
    if (threadIdx.x == 0) {
        __threadfence();
        unsigned arrived = atomicAdd(&g_bar_count, 1u) + 1u;
        if (arrived == (unsigned)NBLK) {
            g_bar_count = 0;
            __threadfence();
            atomicExch(&g_bar_gen, gen + 1u);
        } else {
            unsigned cur;
            do {
                __nanosleep(64);
                asm volatile("ld.global.cg.u32 %0, [%1];" : "=r"(cur) : "l"(&g_bar_gen));
            } while (cur == gen);
        }
        __threadfence();
    }
    __syncthreads();
    gen++;
}

// ---------------- A-tile loaders (M = 128 = full batch; pre-offset by koff where used) ----------------
struct BufLoader {
    const float* A; int lda;
    __device__ __forceinline__ float4 ld(int m, int k) const {
        return cg4(A + (size_t)m * lda + k);
    }
};
struct Mul2Loader {  // A[m][k] = X[m][k] * (Y0[m][k] + Y1[m][k])
    const float* X; const float* Y0; const float* Y1;
    __device__ __forceinline__ float4 ld(int m, int k) const {
        float4 a  = cg4(X  + (size_t)m * H_ + k);
        float4 b0 = cg4(Y0 + (size_t)m * H_ + k);
        float4 b1 = cg4(Y1 + (size_t)m * H_ + k);
        return make_float4(a.x * (b0.x + b1.x), a.y * (b0.y + b1.y),
                           a.z * (b0.z + b1.z), a.w * (b0.w + b1.w));
    }
};
struct Mul4Loader {  // A[m][k] = (X0+X1)[m][k] * (Y0+Y1)[m][k]
    const float* X0; const float* X1; const float* Y0; const float* Y1;
    __device__ __forceinline__ float4 ld(int m, int k) const {
        float4 a0 = cg4(X0 + (size_t)m * H_ + k);
        float4 a1 = cg4(X1 + (size_t)m * H_ + k);
        float4 b0 = cg4(Y0 + (size_t)m * H_ + k);
        float4 b1 = cg4(Y1 + (size_t)m * H_ + k);
        return make_float4((a0.x + a1.x) * (b0.x + b1.x), (a0.y + a1.y) * (b0.y + b1.y),
                           (a0.z + a1.z) * (b0.z + b1.z), (a0.w + a1.w) * (b0.w + b1.w));
    }
};
struct EmbLoader {
    const float* we; const float* ee; const int* sw; const int* se;
    __device__ __forceinline__ float4 ld(int m, int k) const {
        if (k < E_) return *(const float4*)(we + (size_t)sw[m] * E_ + k);
        return *(const float4*)(ee + (size_t)se[m] * XE_ + (k - E_));
    }
};

typedef float SmA[16][128];
typedef float SmW[16][64];

// ---------------- 128x64 tile GEMM: acc += A[128,K] @ Wtile[64,K]^T ----------------
// R8 inner loop (proven best). lda = W row stride, separate from k-extent K.
template <class AL>
__device__ __forceinline__ void gemm_seg(u64 (&acc)[4][4], const AL& al,
                                         const float* __restrict__ W, int K, int lda,
                                         SmA* As, SmW* Ws) {
    const int tid = threadIdx.x;
    const int lm  = tid >> 2;
    const int lk  = (tid & 3) << 2;
    const int tm  = tid >> 4;
    const int tn  = tid & 15;
    float4 a0 = al.ld(lm, lk);
    float4 a1 = al.ld(lm + 64, lk);
    float4 w  = *(const float4*)(W + (size_t)lm * lda + lk);
    const int nch = K >> 4;
    int buf = 0;
    for (int ch = 0; ch < nch; ch++) {
        As[buf][lk + 0][lm] = a0.x; As[buf][lk + 1][lm] = a0.y;
        As[buf][lk + 2][lm] = a0.z; As[buf][lk + 3][lm] = a0.w;
        As[buf][lk + 0][lm + 64] = a1.x; As[buf][lk + 1][lm + 64] = a1.y;
        As[buf][lk + 2][lm + 64] = a1.z; As[buf][lk + 3][lm + 64] = a1.w;
        Ws[buf][lk + 0][lm] = w.x; Ws[buf][lk + 1][lm] = w.y;
        Ws[buf][lk + 2][lm] = w.z; Ws[buf][lk + 3][lm] = w.w;
        __syncthreads();
        if (ch + 1 < nch) {
            a0 = al.ld(lm, ((ch + 1) << 4) + lk);
            a1 = al.ld(lm + 64, ((ch + 1) << 4) + lk);
            w  = *(const float4*)(W + (size_t)lm * lda + ((ch + 1) << 4) + lk);
        }
#pragma unroll
        for (int kk = 0; kk < 16; kk++) {
            ulonglong2 ar0 = *(const ulonglong2*)&As[buf][kk][tm << 3];
            ulonglong2 ar1 = *(const ulonglong2*)&As[buf][kk][(tm << 3) + 4];
            float4 wv = *(const float4*)&Ws[buf][kk][tn << 2];
            u64 wp;
            PACK2(wp, wv.x);
            FMA2(acc[0][0], ar0.x, wp); FMA2(acc[0][1], ar0.y, wp);
            FMA2(acc[0][2], ar1.x, wp); FMA2(acc[0][3], ar1.y, wp);
            PACK2(wp, wv.y);
            FMA2(acc[1][0], ar0.x, wp); FMA2(acc[1][1], ar0.y, wp);
            FMA2(acc[1][2], ar1.x, wp); FMA2(acc[1][3], ar1.y, wp);
            PACK2(wp, wv.z);
            FMA2(acc[2][0], ar0.x, wp); FMA2(acc[2][1], ar0.y, wp);
            FMA2(acc[2][2], ar1.x, wp); FMA2(acc[2][3], ar1.y, wp);
            PACK2(wp, wv.w);
            FMA2(acc[3][0], ar0.x, wp); FMA2(acc[3][1], ar0.y, wp);
            FMA2(acc[3][2], ar1.x, wp); FMA2(acc[3][3], ar1.y, wp);
        }
        buf ^= 1;
    }
    __syncthreads();
}

__device__ __forceinline__ void store_tile(float* __restrict__ C, int ldc, int c0,
                                           u64 (&acc)[4][4], const float* __restrict__ bias) {
    const int tid = threadIdx.x;
    const int tm = tid >> 4, tn = tid & 15;
    float4 bv = make_float4(0.f, 0.f, 0.f, 0.f);
    if (bias) bv = *(const float4*)(bias + (tn << 2));
#pragma unroll
    for (int rp = 0; rp < 4; rp++) {
        unsigned l0, h0, l1, h1, l2, h2, l3, h3;
        UNPACK2(l0, h0, acc[0][rp]);
        UNPACK2(l1, h1, acc[1][rp]);
        UNPACK2(l2, h2, acc[2][rp]);
        UNPACK2(l3, h3, acc[3][rp]);
        const int r0 = (tm << 3) + (rp << 1);
        *(float4*)(C + (size_t)r0 * ldc + c0 + (tn << 2)) =
            make_float4(__uint_as_float(l0) + bv.x, __uint_as_float(l1) + bv.y,
                        __uint_as_float(l2) + bv.z, __uint_as_float(l3) + bv.w);
        *(float4*)(C + (size_t)(r0 + 1) * ldc + c0 + (tn << 2)) =
            make_float4(__uint_as_float(h0) + bv.x, __uint_as_float(h1) + bv.y,
                        __uint_as_float(h2) + bv.z, __uint_as_float(h3) + bv.w);
    }
}

// ---------------- P6 body: cell2 gates (flag-gated) + write outs[:,t,:] ----------------
__device__ __forceinline__ void do_p6(int b, int t, float s_flag,
                                      float* __restrict__ out, float* __restrict__ out_flags) {
    const int tid = threadIdx.x;
    const bool upd = s_flag > 0.5f;
    const int j = tid << 2;
    const size_t o = (size_t)b * H_ + j;
    float4 h2v = *(const float4*)&g_h2[o];
    if (upd) {
        const size_t z = (size_t)b * H4_ + j;
        float4 zi = cg4(&g_z2[z]);             float4 ziB = cg4(&g_z2B[z]);
        float4 pi0 = cg4(&g_z2p0[z]);          float4 pi1 = cg4(&g_z2p1[z]);
        float4 zf = cg4(&g_z2[z + H_]);        float4 zfB = cg4(&g_z2B[z + H_]);
        float4 pf0 = cg4(&g_z2p0[z + H_]);     float4 pf1 = cg4(&g_z2p1[z + H_]);
        float4 zg = cg4(&g_z2[z + 2 * H_]);    float4 zgB = cg4(&g_z2B[z + 2 * H_]);
        float4 pg0 = cg4(&g_z2p0[z + 2 * H_]); float4 pg1 = cg4(&g_z2p1[z + 2 * H_]);
        float4 zo = cg4(&g_z2[z + 3 * H_]);    float4 zoB = cg4(&g_z2B[z + 3 * H_]);
        float4 po0 = cg4(&g_z2p0[z + 3 * H_]); float4 po1 = cg4(&g_z2p1[z + 3 * H_]);
        float4 c2v = *(const float4*)&g_c2[o];
        float xi[4] = {zi.x + ziB.x + pi0.x + pi1.x, zi.y + ziB.y + pi0.y + pi1.y,
                       zi.z + ziB.z + pi0.z + pi1.z, zi.w + ziB.w + pi0.w + pi1.w};
        float xf[4] = {zf.x + zfB.x + pf0.x + pf1.x, zf.y + zfB.y + pf0.y + pf1.y,
                       zf.z + zfB.z + pf0.z + pf1.z, zf.w + zfB.w + pf0.w + pf1.w};
        float xg[4] = {zg.x + zgB.x + pg0.x + pg1.x, zg.y + zgB.y + pg0.y + pg1.y,
                       zg.z + zgB.z + pg0.z + pg1.z, zg.w + zgB.w + pg0.w + pg1.w};
        float xo[4] = {zo.x + zoB.x + po0.x + po1.x, zo.y + zoB.y + po0.y + po1.y,
                       zo.z + zoB.z + po0.z + po1.z, zo.w + zoB.w + po0.w + po1.w};
        float cv[4] = {c2v.x, c2v.y, c2v.z, c2v.w};
        float hn[4], cn[4];
#pragma unroll
        for (int q = 0; q < 4; q++) {
            cn[q] = sigf(xf[q]) * cv[q] + sigf(xi[q]) * tanhf(xg[q]);
            hn[q] = sigf(xo[q]) * tanhf(cn[q]);
        }
        h2v = make_float4(hn[0], hn[1], hn[2], hn[3]);
        *(float4*)&g_h2[o] = h2v;
        *(float4*)&g_c2[o] = make_float4(cn[0], cn[1], cn[2], cn[3]);
    }
    *(float4*)&out[(size_t)b * S_ * H_ + (size_t)t * H_ + j] = h2v;
    if (b == 0 && tid == 0 && out_flags) out_flags[t] = s_flag;
}

// ---------------- the single persistent kernel ----------------
__global__ __launch_bounds__(NTHR, 2) void enc_kernel(
    const int* __restrict__ enc, const int* __restrict__ encx,
    const float* __restrict__ we, const float* __restrict__ ee,
    const float* __restrict__ Wsi, const float* __restrict__ Wsh,
    const float* __restrict__ b_bd, const float* __restrict__ vs,
    const float* __restrict__ Wmx1, const float* __restrict__ Wmh1,
    const float* __restrict__ Wih1, const float* __restrict__ Whh1, const float* __restrict__ b1,
    const float* __restrict__ Wmx2, const float* __restrict__ Wmh2,
    const float* __restrict__ Wih2, const float* __restrict__ Whh2, const float* __restrict__ b2,
    float* __restrict__ out, float* __restrict__ out_h2,
    float* __restrict__ out_c2, float* __restrict__ out_flags) {
    __shared__ float As[2][16][128];
    __shared__ float Ws[2][16][64];
    __shared__ float red[NTHR];
    __shared__ int sw[128], se[128];
    const int tid = threadIdx.x;
    const int bid = blockIdx.x;
    unsigned gen = *((volatile unsigned*)&g_bar_gen);

    // init: zero recurrent state (h1=0 initially -> h1z starts TRUE; zbb/mh never read stale)
    for (int i = bid * NTHR + tid; i < B_ * H_; i += NBLK * NTHR) {
        g_h1[i] = 0.f; g_c1[i] = 0.f; g_h2[i] = 0.f; g_c2[i] = 0.f;
    }

    // ---- PRECOMPUTE: all x-side GEMMs for every step (no recurrent dependency).
    for (int task = bid; task < S_ * 88; task += NBLK) {
        const int t  = task / 88;
        const int ct = task - t * 88;
        if (tid < 128) {
            sw[tid] = enc[(size_t)tid * S_ + t];
            se[tid] = encx[(size_t)tid * S_ + t];
        }
        __syncthreads();
        u64 acc[4][4] = {};
        EmbLoader el{we, ee, sw, se};
        if (ct < 8) {
            const int c0 = ct << 6;
            gemm_seg(acc, el, Wsi + (size_t)c0 * FEAT_, FEAT_, FEAT_, As, Ws);
            store_tile(g_zba_all + (size_t)t * B_ * MID_, MID_, c0, acc, b_bd + c0);
        } else if (ct < 24) {
            const int c0 = (ct - 8) << 6;
            gemm_seg(acc, el, Wmx1 + (size_t)c0 * FEAT_, FEAT_, FEAT_, As, Ws);
            store_tile(g_mx_all + (size_t)t * B_ * H_, H_, c0, acc, nullptr);
        } else {
            const int c0 = (ct - 24) << 6;
            gemm_seg(acc, el, Wih1 + (size_t)c0 * FEAT_, FEAT_, FEAT_, As, Ws);
            store_tile(g_z1_all + (size_t)t * B_ * H4_, H4_, c0, acc, b1 + c0);
        }
    }
    grid_barrier(gen);

    float s_prev = 0.f;   // flag of step t-1 (uniform)
    bool  h1z    = true;  // h1 entering step t is exactly zero (t=0: yes; else = s_prev>0.5)

    for (int t = 0; t < S_; t++) {
        // ---- PHASE_BC (XOR): h1 nonzero -> P2(t); h1 zero & prev flagged -> P5(t-1).
        //      (After a flagged step, mh==0 -> z1p==0 -> P2 result is all zeros: skip it.)
        if (!h1z) {
            if (bid < 128) {
                const int r = bid;
                const int c0 = (r >> 1) << 6;
                const int koff = (r & 1) << 9;
                u64 acc[4][4] = {};
                Mul2Loader ml{g_mx_all + (size_t)t * B_ * H_ + koff, g_mh + koff, g_mhB + koff};
                gemm_seg(acc, ml, Whh1 + (size_t)c0 * H_ + koff, 512, H_, As, Ws);
                store_tile((r & 1) ? g_z1p1 : g_z1p0, H4_, c0, acc, nullptr);
            }
        } else if (t > 0 && s_prev > 0.5f) {
            if (bid < 128) {
                const int r = bid;
                const int c0 = (r >> 1) << 6;
                const int koff = (r & 1) << 9;
                u64 acc[4][4] = {};
                Mul4Loader ml{g_mx2 + koff, g_mx2B + koff, g_mh2 + koff, g_mh2B + koff};
                gemm_seg(acc, ml, Whh2 + (size_t)c0 * H_ + koff, 512, H_, As, Ws);
                store_tile((r & 1) ? g_z2p1 : g_z2p0, H4_, c0, acc, nullptr);
            }
        }
        grid_barrier(gen);

        // ---- PHASE_CD: P3(t) on 0..127 || P6(t-1) on 168..295.
        if (bid < B_) {
            const int b = bid;
            const float* zba = g_zba_all + (size_t)t * B_ * MID_;
            float v;
            if (h1z) {
                // zbb==0: boundary dot from precomputed zba only
                v = cg1(&zba[(size_t)b * MID_ + tid]) * vs[tid] +
                    cg1(&zba[(size_t)b * MID_ + 256 + tid]) * vs[256 + tid];
            } else {
                v = (cg1(&zba[(size_t)b * MID_ + tid]) + cg1(&g_zbb[(size_t)b * MID_ + tid]) +
                     cg1(&g_zbbB[(size_t)b * MID_ + tid])) * vs[tid] +
                    (cg1(&zba[(size_t)b * MID_ + 256 + tid]) + cg1(&g_zbb[(size_t)b * MID_ + 256 + tid]) +
                     cg1(&g_zbbB[(size_t)b * MID_ + 256 + tid])) * vs[256 + tid];
            }
            red[tid] = v;
            __syncthreads();
            for (int off = 128; off > 0; off >>= 1) {
                if (tid < off) red[tid] += red[tid + off];
                __syncthreads();
            }
            const float s = (red[0] > 0.f) ? 1.f : 0.f;
            if (tid == 0) g_s[b] = s;
            {
                const int j = tid << 2;
                const size_t o = (size_t)b * H_ + j;
                const float* z1 = g_z1_all + (size_t)t * B_ * H4_;
                const size_t z = (size_t)b * H4_ + j;
                float4 zi = cg4(&z1[z]);
                float4 zf = cg4(&z1[z + H_]);
                float4 zg = cg4(&z1[z + 2 * H_]);
                float4 zo = cg4(&z1[z + 3 * H_]);
                const float4 z4 = make_float4(0.f, 0.f, 0.f, 0.f);
                float4 pi0 = z4, pi1 = z4, pf0 = z4, pf1 = z4,
                       pg0 = z4, pg1 = z4, po0 = z4, po1 = z4;
                if (!h1z) {   // z1p valid only when P2 ran; otherwise contribution is exactly 0
                    pi0 = cg4(&g_z1p0[z]);          pi1 = cg4(&g_z1p1[z]);
                    pf0 = cg4(&g_z1p0[z + H_]);     pf1 = cg4(&g_z1p1[z + H_]);
                    pg0 = cg4(&g_z1p0[z + 2 * H_]); pg1 = cg4(&g_z1p1[z + 2 * H_]);
                    po0 = cg4(&g_z1p0[z + 3 * H_]); po1 = cg4(&g_z1p1[z + 3 * H_]);
                }
                float4 c1v = *(const float4*)&g_c1[o];
                float xi[4] = {zi.x + pi0.x + pi1.x, zi.y + pi0.y + pi1.y, zi.z + pi0.z + pi1.z, zi.w + pi0.w + pi1.w};
                float xf[4] = {zf.x + pf0.x + pf1.x, zf.y + pf0.y + pf1.y, zf.z + pf0.z + pf1.z, zf.w + pf0.w + pf1.w};
                float xg[4] = {zg.x + pg0.x + pg1.x, zg.y + pg0.y + pg1.y, zg.z + pg0.z + pg1.z, zg.w + pg0.w + pg1.w};
                float xo[4] = {zo.x + po0.x + po1.x, zo.y + po0.y + po1.y, zo.z + po0.z + po1.z, zo.w + po0.w + po1.w};
                float cv[4] = {c1v.x, c1v.y, c1v.z, c1v.w};
                float x2v[4], h1v[4], c1n[4];
#pragma unroll
                for (int q = 0; q < 4; q++) {
                    float cn = sigf(xf[q]) * cv[q] + sigf(xi[q]) * tanhf(xg[q]);
                    float hn = sigf(xo[q]) * tanhf(cn);
                    x2v[q] = hn * s;
                    h1v[q] = hn * (1.f - s);
                    c1n[q] = cn * (1.f - s);
                }
                *(float4*)&g_x2[o] = make_float4(x2v[0], x2v[1], x2v[2], x2v[3]);
                *(float4*)&g_h1[o] = make_float4(h1v[0], h1v[1], h1v[2], h1v[3]);
                *(float4*)&g_c1[o] = make_float4(c1n[0], c1n[1], c1n[2], c1n[3]);
            }
        } else if (bid >= 168 && t > 0) {
            do_p6(bid - 168, t - 1, s_prev, out, out_flags);
        }
        grid_barrier(gen);

        const float s_cur = cg1(&g_s[0]);

        // ---- PHASE_A (XOR): flagged -> P4 split only (h1 now 0 -> P1' output would be 0);
        //      unflagged -> P1' split only (no cell-2 work).
        if (s_cur > 0.5f) {
            if (bid < 192) {
                const int ct = bid % 96;
                const int kh = bid / 96;
                const int koff = kh << 9;
                u64 acc[4][4] = {};
                if (ct < 16) {
                    const int c0 = ct << 6;
                    BufLoader bl{g_x2 + koff, H_};
                    gemm_seg(acc, bl, Wmx2 + (size_t)c0 * H_ + koff, 512, H_, As, Ws);
                    store_tile(kh ? g_mx2B : g_mx2, H_, c0, acc, nullptr);
                } else if (ct < 32) {
                    const int c0 = (ct - 16) << 6;
                    BufLoader bl{g_h2 + koff, H_};
                    gemm_seg(acc, bl, Wmh2 + (size_t)c0 * H_ + koff, 512, H_, As, Ws);
                    store_tile(kh ? g_mh2B : g_mh2, H_, c0, acc, nullptr);
                } else {
                    const int c0 = (ct - 32) << 6;
                    BufLoader bl{g_x2 + koff, H_};
                    gemm_seg(acc, bl, Wih2 + (size_t)c0 * H_ + koff, 512, H_, As, Ws);
                    store_tile(kh ? g_z2B : g_z2, H4_, c0, acc, kh ? nullptr : (b2 + c0));
                }
            }
        } else {
            if (bid < 48) {
                const int p  = bid % 24;
                const int kh = bid / 24;
                const int koff = kh << 9;
                u64 acc[4][4] = {};
                BufLoader bl{g_h1 + koff, H_};
                if (p < 8) {
                    const int c0 = p << 6;
                    gemm_seg(acc, bl, Wsh + (size_t)c0 * H_ + koff, 512, H_, As, Ws);
                    store_tile(kh ? g_zbbB : g_zbb, MID_, c0, acc, nullptr);
                } else {
                    const int c0 = (p - 8) << 6;
                    gemm_seg(acc, bl, Wmh1 + (size_t)c0 * H_ + koff, 512, H_, As, Ws);
                    store_tile(kh ? g_mhB : g_mh, H_, c0, acc, nullptr);
                }
            }
        }
        grid_barrier(gen);

        s_prev = s_cur;
        h1z = (s_cur > 0.5f);
    }

    // ---- epilogue: P5(S-1) if flagged, then P6(S-1), then final state copy.
    if (s_prev > 0.5f) {
        if (bid < 128) {
            const int r = bid;
            const int c0 = (r >> 1) << 6;
            const int koff = (r & 1) << 9;
            u64 acc[4][4] = {};
            Mul4Loader ml{g_mx2 + koff, g_mx2B + koff, g_mh2 + koff, g_mh2B + koff};
            gemm_seg(acc, ml, Whh2 + (size_t)c0 * H_ + koff, 512, H_, As, Ws);
            store_tile((r & 1) ? g_z2p1 : g_z2p0, H4_, c0, acc, nullptr);
        }
        grid_barrier(gen);
    }
    if (bid >= 168) {
        do_p6(bid - 168, S_ - 1, s_prev, out, out_flags);
    }
    grid_barrier(gen);
    if (out_h2) {
        for (int i = bid * NTHR + tid; i < B_ * H_; i += NBLK * NTHR) {
            out_h2[i] = cg1(&g_h2[i]);
            out_c2[i] = cg1(&g_c2[i]);
        }
    }
}

// ---------------- host: exactly ONE graph node ----------------
extern "C" void kernel_launch(void* const* d_in, const int* in_sizes, int n_in,
                              void* d_out, int out_size) {
    const int*   enc   = (const int*)d_in[0];
    const int*   encx  = (const int*)d_in[1];
    const float* we    = (const float*)d_in[2];
    const float* ee    = (const float*)d_in[3];
    const float* Wsi   = (const float*)d_in[4];
    const float* Wsh   = (const float*)d_in[5];
    const float* b_bd  = (const float*)d_in[6];
    const float* vs    = (const float*)d_in[7];
    const float* Wmx1  = (const float*)d_in[8];
    const float* Wmh1  = (const float*)d_in[9];
    const float* Wih1  = (const float*)d_in[10];
    const float* Whh1  = (const float*)d_in[11];
    const float* b1    = (const float*)d_in[12];
    const float* Wmx2  = (const float*)d_in[13];
    const float* Wmh2  = (const float*)d_in[14];
    const float* Wih2  = (const float*)d_in[15];
    const float* Whh2  = (const float*)d_in[16];
    const float* b2    = (const float*)d_in[17];
    float* out = (float*)d_out;

    const size_t outs_elems  = (size_t)B_ * S_ * H_;
    const size_t state_elems = (size_t)B_ * H_;
    float* out_h2 = nullptr;
    float* out_c2 = nullptr;
    float* out_flags = nullptr;
    if ((size_t)out_size >= outs_elems + 2 * state_elems + S_) {
        out_h2 = out + outs_elems;
        out_c2 = out_h2 + state_elems;
        out_flags = out_c2 + state_elems;
    }

    enc_kernel<<<NBLK, NTHR>>>(enc, encx, we, ee, Wsi, Wsh, b_bd, vs,
                               Wmx1, Wmh1, Wih1, Whh1, b1,
                               Wmx2, Wmh2, Wih2, Whh2, b2,
                               out, out_h2, out_c2, out_flags);
    (void)in_sizes; (void)n_in;
}

// round 17
// speedup vs baseline: 1.4669x; 1.0982x over previous
#include <cuda_runtime.h>
#include <cstdint>

#define B_    128
#define S_    512
#define H_    1024
#define MID_  512
#define E_    512
#define XE_   64
#define FEAT_ 576
#define H4_   4096
#define NBLK  296
#define NTHR  256

typedef unsigned long long u64;

// ---------------- persistent state + scratch (device globals; no allocs) ----------------
__device__ float g_h1[B_ * H_];
__device__ float g_c1[B_ * H_];
__device__ float g_h2[B_ * H_];
__device__ float g_c2[B_ * H_];
__device__ float g_zbbq[4][B_ * MID_];   // h-side boundary partials, k-quarters
__device__ float g_mhq[4][B_ * H_];      // mh partials, k-quarters
__device__ float g_z1p[4][B_ * H4_];     // P2 output partials (k-quarters)
__device__ float g_x2[B_ * H_];
__device__ float g_mx2q[4][B_ * H_];     // P4 outputs, k-quarters
__device__ float g_mh2q[4][B_ * H_];
__device__ float g_z2q[4][B_ * H4_];     // quarter 0 carries +bias
__device__ float g_z2p[4][B_ * H4_];     // P5 output partials
__device__ float g_s[B_];
__device__ unsigned g_bar_count = 0;
__device__ unsigned g_bar_gen = 0;
// precomputed x-side results for ALL steps (input-only dependent)
__device__ float g_zba_all[S_ * B_ * MID_];
__device__ float g_mx_all[S_ * B_ * H_];
__device__ float g_z1_all[S_ * B_ * H4_];

__device__ __forceinline__ float sigf(float x) { return 1.f / (1.f + expf(-x)); }
__device__ __forceinline__ float4 cg4(const float* p) { return __ldcg((const float4*)p); }
__device__ __forceinline__ float  cg1(const float* p) { return __ldcg(p); }

#define FMA2(acc, a, b) asm("fma.rn.f32x2 %0, %1, %2, %0;" : "+l"(acc) : "l"(a), "l"(b))
#define PACK2(d, f)     asm("mov.b64 %0, {%1, %1};" : "=l"(d) : "r"(__float_as_uint(f)))
#define UNPACK2(lo, hi, v) asm("mov.b64 {%0, %1}, %2;" : "=r"(lo), "=r"(hi) : "l"(v))

// ---------------- grid-wide barrier (all NBLK blocks co-resident: 2 CTAs x 148 SMs) ----------------
__device__ __forceinline__ void grid_barrier(unsigned& gen) {
    __syncthreads();
    if (threadIdx.x == 0) {
        __threadfence();
        unsigned arrived = atomicAdd(&g_bar_count, 1u) + 1u;
        if (arrived == (unsigned)NBLK) {
            g_bar_count = 0;
            __threadfence();
            atomicExch(&g_bar_gen, gen + 1u);
        } else {
            unsigned cur;
            do {
                __nanosleep(64);
                asm volatile("ld.global.cg.u32 %0, [%1];" : "=r"(cur) : "l"(&g_bar_gen));
            } while (cur == gen);
        }
        __threadfence();
    }
    __syncthreads();
    gen++;
}

// ---------------- A-tile loaders (M = 128 = full batch; pre-offset by koff where used) ----------------
struct BufLoader {
    const float* A; int lda;
    __device__ __forceinline__ float4 ld(int m, int k) const {
        return cg4(A + (size_t)m * lda + k);
    }
};
struct MulS4Loader {  // A[m][k] = X[m][k] * (Y0+Y1+Y2+Y3)[m][k]
    const float* X; const float* Y0; const float* Y1; const float* Y2; const float* Y3;
    __device__ __forceinline__ float4 ld(int m, int k) const {
        const size_t o = (size_t)m * H_ + k;
        float4 a  = cg4(X + o);
        float4 b0 = cg4(Y0 + o); float4 b1 = cg4(Y1 + o);
        float4 b2 = cg4(Y2 + o); float4 b3 = cg4(Y3 + o);
        return make_float4(a.x * (b0.x + b1.x + b2.x + b3.x),
                           a.y * (b0.y + b1.y + b2.y + b3.y),
                           a.z * (b0.z + b1.z + b2.z + b3.z),
                           a.w * (b0.w + b1.w + b2.w + b3.w));
    }
};
struct MulS44Loader {  // A[m][k] = (X0+..+X3)[m][k] * (Y0+..+Y3)[m][k]
    const float* X0; const float* X1; const float* X2; const float* X3;
    const float* Y0; const float* Y1; const float* Y2; const float* Y3;
    __device__ __forceinline__ float4 ld(int m, int k) const {
        const size_t o = (size_t)m * H_ + k;
        float4 a0 = cg4(X0 + o); float4 a1 = cg4(X1 + o);
        float4 a2 = cg4(X2 + o); float4 a3 = cg4(X3 + o);
        float4 b0 = cg4(Y0 + o); float4 b1 = cg4(Y1 + o);
        float4 b2 = cg4(Y2 + o); float4 b3 = cg4(Y3 + o);
        return make_float4((a0.x + a1.x + a2.x + a3.x) * (b0.x + b1.x + b2.x + b3.x),
                           (a0.y + a1.y + a2.y + a3.y) * (b0.y + b1.y + b2.y + b3.y),
                           (a0.z + a1.z + a2.z + a3.z) * (b0.z + b1.z + b2.z + b3.z),
                           (a0.w + a1.w + a2.w + a3.w) * (b0.w + b1.w + b2.w + b3.w));
    }
};
struct EmbLoader {
    const float* we; const float* ee; const int* sw; const int* se;
    __device__ __forceinline__ float4 ld(int m, int k) const {
        if (k < E_) return *(const float4*)(we + (size_t)sw[m] * E_ + k);
        return *(const float4*)(ee + (size_t)se[m] * XE_ + (k - E_));
    }
};

typedef float SmA[16][128];
typedef float SmW[16][64];

// ---------------- 128x64 tile GEMM: acc += A[128,K] @ Wtile[64,K]^T ----------------
// R8 inner loop (proven best). lda = W row stride, separate from k-extent K.
template <class AL>
__device__ __forceinline__ void gemm_seg(u64 (&acc)[4][4], const AL& al,
                                         const float* __restrict__ W, int K, int lda,
                                         SmA* As, SmW* Ws) {
    const int tid = threadIdx.x;
    const int lm  = tid >> 2;
    const int lk  = (tid & 3) << 2;
    const int tm  = tid >> 4;
    const int tn  = tid & 15;
    float4 a0 = al.ld(lm, lk);
    float4 a1 = al.ld(lm + 64, lk);
    float4 w  = *(const float4*)(W + (size_t)lm * lda + lk);
    const int nch = K >> 4;
    int buf = 0;
    for (int ch = 0; ch < nch; ch++) {
        As[buf][lk + 0][lm] = a0.x; As[buf][lk + 1][lm] = a0.y;
        As[buf][lk + 2][lm] = a0.z; As[buf][lk + 3][lm] = a0.w;
        As[buf][lk + 0][lm + 64] = a1.x; As[buf][lk + 1][lm + 64] = a1.y;
        As[buf][lk + 2][lm + 64] = a1.z; As[buf][lk + 3][lm + 64] = a1.w;
        Ws[buf][lk + 0][lm] = w.x; Ws[buf][lk + 1][lm] = w.y;
        Ws[buf][lk + 2][lm] = w.z; Ws[buf][lk + 3][lm] = w.w;
        __syncthreads();
        if (ch + 1 < nch) {
            a0 = al.ld(lm, ((ch + 1) << 4) + lk);
            a1 = al.ld(lm + 64, ((ch + 1) << 4) + lk);
            w  = *(const float4*)(W + (size_t)lm * lda + ((ch + 1) << 4) + lk);
        }
#pragma unroll
        for (int kk = 0; kk < 16; kk++) {
            ulonglong2 ar0 = *(const ulonglong2*)&As[buf][kk][tm << 3];
            ulonglong2 ar1 = *(const ulonglong2*)&As[buf][kk][(tm << 3) + 4];
            float4 wv = *(const float4*)&Ws[buf][kk][tn << 2];
            u64 wp;
            PACK2(wp, wv.x);
            FMA2(acc[0][0], ar0.x, wp); FMA2(acc[0][1], ar0.y, wp);
            FMA2(acc[0][2], ar1.x, wp); FMA2(acc[0][3], ar1.y, wp);
            PACK2(wp, wv.y);
            FMA2(acc[1][0], ar0.x, wp); FMA2(acc[1][1], ar0.y, wp);
            FMA2(acc[1][2], ar1.x, wp); FMA2(acc[1][3], ar1.y, wp);
            PACK2(wp, wv.z);
            FMA2(acc[2][0], ar0.x, wp); FMA2(acc[2][1], ar0.y, wp);
            FMA2(acc[2][2], ar1.x, wp); FMA2(acc[2][3], ar1.y, wp);
            PACK2(wp, wv.w);
            FMA2(acc[3][0], ar0.x, wp); FMA2(acc[3][1], ar0.y, wp);
            FMA2(acc[3][2], ar1.x, wp); FMA2(acc[3][3], ar1.y, wp);
        }
        buf ^= 1;
    }
    __syncthreads();
}

__device__ __forceinline__ void store_tile(float* __restrict__ C, int ldc, int c0,
                                           u64 (&acc)[4][4], const float* __restrict__ bias) {
    const int tid = threadIdx.x;
    const int tm = tid >> 4, tn = tid & 15;
    float4 bv = make_float4(0.f, 0.f, 0.f, 0.f);
    if (bias) bv = *(const float4*)(bias + (tn << 2));
#pragma unroll
    for (int rp = 0; rp < 4; rp++) {
        unsigned l0, h0, l1, h1, l2, h2, l3, h3;
        UNPACK2(l0, h0, acc[0][rp]);
        UNPACK2(l1, h1, acc[1][rp]);
        UNPACK2(l2, h2, acc[2][rp]);
        UNPACK2(l3, h3, acc[3][rp]);
        const int r0 = (tm << 3) + (rp << 1);
        *(float4*)(C + (size_t)r0 * ldc + c0 + (tn << 2)) =
            make_float4(__uint_as_float(l0) + bv.x, __uint_as_float(l1) + bv.y,
                        __uint_as_float(l2) + bv.z, __uint_as_float(l3) + bv.w);
        *(float4*)(C + (size_t)(r0 + 1) * ldc + c0 + (tn << 2)) =
            make_float4(__uint_as_float(h0) + bv.x, __uint_as_float(h1) + bv.y,
                        __uint_as_float(h2) + bv.z, __uint_as_float(h3) + bv.w);
    }
}

__device__ __forceinline__ float4 sum8q(const float* q0, const float* q1, const float* q2, const float* q3,
                                        const float* p0, const float* p1, const float* p2, const float* p3,
                                        size_t z) {
    float4 a0 = cg4(q0 + z), a1 = cg4(q1 + z), a2 = cg4(q2 + z), a3 = cg4(q3 + z);
    float4 b0 = cg4(p0 + z), b1 = cg4(p1 + z), b2 = cg4(p2 + z), b3 = cg4(p3 + z);
    return make_float4(a0.x + a1.x + a2.x + a3.x + b0.x + b1.x + b2.x + b3.x,
                       a0.y + a1.y + a2.y + a3.y + b0.y + b1.y + b2.y + b3.y,
                       a0.z + a1.z + a2.z + a3.z + b0.z + b1.z + b2.z + b3.z,
                       a0.w + a1.w + a2.w + a3.w + b0.w + b1.w + b2.w + b3.w);
}

// ---------------- P6 body: cell2 gates (flag-gated) + write outs[:,t,:] ----------------
__device__ __forceinline__ void do_p6(int b, int t, float s_flag,
                                      float* __restrict__ out, float* __restrict__ out_flags) {
    const int tid = threadIdx.x;
    const bool upd = s_flag > 0.5f;
    const int j = tid << 2;
    const size_t o = (size_t)b * H_ + j;
    float4 h2v = *(const float4*)&g_h2[o];
    if (upd) {
        const size_t z = (size_t)b * H4_ + j;
        float4 xiv = sum8q(g_z2q[0], g_z2q[1], g_z2q[2], g_z2q[3],
                           g_z2p[0], g_z2p[1], g_z2p[2], g_z2p[3], z);
        float4 xfv = sum8q(g_z2q[0], g_z2q[1], g_z2q[2], g_z2q[3],
                           g_z2p[0], g_z2p[1], g_z2p[2], g_z2p[3], z + H_);
        float4 xgv = sum8q(g_z2q[0], g_z2q[1], g_z2q[2], g_z2q[3],
                           g_z2p[0], g_z2p[1], g_z2p[2], g_z2p[3], z + 2 * H_);
        float4 xov = sum8q(g_z2q[0], g_z2q[1], g_z2q[2], g_z2q[3],
                           g_z2p[0], g_z2p[1], g_z2p[2], g_z2p[3], z + 3 * H_);
        float4 c2v = *(const float4*)&g_c2[o];
        float xi[4] = {xiv.x, xiv.y, xiv.z, xiv.w};
        float xf[4] = {xfv.x, xfv.y, xfv.z, xfv.w};
        float xg[4] = {xgv.x, xgv.y, xgv.z, xgv.w};
        float xo[4] = {xov.x, xov.y, xov.z, xov.w};
        float cv[4] = {c2v.x, c2v.y, c2v.z, c2v.w};
        float hn[4], cn[4];
#pragma unroll
        for (int q = 0; q < 4; q++) {
            cn[q] = sigf(xf[q]) * cv[q] + sigf(xi[q]) * tanhf(xg[q]);
            hn[q] = sigf(xo[q]) * tanhf(cn[q]);
        }
        h2v = make_float4(hn[0], hn[1], hn[2], hn[3]);
        *(float4*)&g_h2[o] = h2v;
        *(float4*)&g_c2[o] = make_float4(cn[0], cn[1], cn[2], cn[3]);
    }
    *(float4*)&out[(size_t)b * S_ * H_ + (size_t)t * H_ + j] = h2v;
    if (b == 0 && tid == 0 && out_flags) out_flags[t] = s_flag;
}

// ---------------- the single persistent kernel ----------------
__global__ __launch_bounds__(NTHR, 2) void enc_kernel(
    const int* __restrict__ enc, const int* __restrict__ encx,
    const float* __restrict__ we, const float* __restrict__ ee,
    const float* __restrict__ Wsi, const float* __restrict__ Wsh,
    const float* __restrict__ b_bd, const float* __restrict__ vs,
    const float* __restrict__ Wmx1, const float* __restrict__ Wmh1,
    const float* __restrict__ Wih1, const float* __restrict__ Whh1, const float* __restrict__ b1,
    const float* __restrict__ Wmx2, const float* __restrict__ Wmh2,
    const float* __restrict__ Wih2, const float* __restrict__ Whh2, const float* __restrict__ b2,
    float* __restrict__ out, float* __restrict__ out_h2,
    float* __restrict__ out_c2, float* __restrict__ out_flags) {
    __shared__ float As[2][16][128];
    __shared__ float Ws[2][16][64];
    __shared__ float red[NTHR];
    __shared__ int sw[128], se[128];
    const int tid = threadIdx.x;
    const int bid = blockIdx.x;
    unsigned gen = *((volatile unsigned*)&g_bar_gen);

    // init: zero recurrent state (h1z starts TRUE; quarter partials always written before read)
    for (int i = bid * NTHR + tid; i < B_ * H_; i += NBLK * NTHR) {
        g_h1[i] = 0.f; g_c1[i] = 0.f; g_h2[i] = 0.f; g_c2[i] = 0.f;
    }

    // ---- PRECOMPUTE: all x-side GEMMs for every step (no recurrent dependency).
    for (int task = bid; task < S_ * 88; task += NBLK) {
        const int t  = task / 88;
        const int ct = task - t * 88;
        if (tid < 128) {
            sw[tid] = enc[(size_t)tid * S_ + t];
            se[tid] = encx[(size_t)tid * S_ + t];
        }
        __syncthreads();
        u64 acc[4][4] = {};
        EmbLoader el{we, ee, sw, se};
        if (ct < 8) {
            const int c0 = ct << 6;
            gemm_seg(acc, el, Wsi + (size_t)c0 * FEAT_, FEAT_, FEAT_, As, Ws);
            store_tile(g_zba_all + (size_t)t * B_ * MID_, MID_, c0, acc, b_bd + c0);
        } else if (ct < 24) {
            const int c0 = (ct - 8) << 6;
            gemm_seg(acc, el, Wmx1 + (size_t)c0 * FEAT_, FEAT_, FEAT_, As, Ws);
            store_tile(g_mx_all + (size_t)t * B_ * H_, H_, c0, acc, nullptr);
        } else {
            const int c0 = (ct - 24) << 6;
            gemm_seg(acc, el, Wih1 + (size_t)c0 * FEAT_, FEAT_, FEAT_, As, Ws);
            store_tile(g_z1_all + (size_t)t * B_ * H4_, H4_, c0, acc, b1 + c0);
        }
    }
    grid_barrier(gen);

    float s_prev = 0.f;   // flag of step t-1 (uniform)
    bool  h1z    = true;  // h1 entering step t is exactly zero

    for (int t = 0; t < S_; t++) {
        // ---- PHASE_BC (XOR): h1 nonzero -> P2(t); h1 zero & prev flagged -> P5(t-1).
        //      256 quarter-tasks on blocks 0..255 (both CTA slots busy on 108 SMs).
        if (!h1z) {
            if (bid < 256) {
                const int c0 = (bid >> 2) << 6;
                const int kq = bid & 3;
                const int koff = kq << 8;
                u64 acc[4][4] = {};
                MulS4Loader ml{g_mx_all + (size_t)t * B_ * H_ + koff,
                               g_mhq[0] + koff, g_mhq[1] + koff, g_mhq[2] + koff, g_mhq[3] + koff};
                gemm_seg(acc, ml, Whh1 + (size_t)c0 * H_ + koff, 256, H_, As, Ws);
                store_tile(g_z1p[kq], H4_, c0, acc, nullptr);
            }
        } else if (t > 0 && s_prev > 0.5f) {
            if (bid < 256) {
                const int c0 = (bid >> 2) << 6;
                const int kq = bid & 3;
                const int koff = kq << 8;
                u64 acc[4][4] = {};
                MulS44Loader ml{g_mx2q[0] + koff, g_mx2q[1] + koff, g_mx2q[2] + koff, g_mx2q[3] + koff,
                                g_mh2q[0] + koff, g_mh2q[1] + koff, g_mh2q[2] + koff, g_mh2q[3] + koff};
                gemm_seg(acc, ml, Whh2 + (size_t)c0 * H_ + koff, 256, H_, As, Ws);
                store_tile(g_z2p[kq], H4_, c0, acc, nullptr);
            }
        }
        grid_barrier(gen);

        // ---- PHASE_CD: P3(t) on 0..127 || P6(t-1) on 168..295.
        if (bid < B_) {
            const int b = bid;
            const float* zba = g_zba_all + (size_t)t * B_ * MID_;
            float v;
            if (h1z) {
                v = cg1(&zba[(size_t)b * MID_ + tid]) * vs[tid] +
                    cg1(&zba[(size_t)b * MID_ + 256 + tid]) * vs[256 + tid];
            } else {
                const size_t i0 = (size_t)b * MID_ + tid;
                const size_t i1 = i0 + 256;
                v = (cg1(&zba[i0]) + cg1(&g_zbbq[0][i0]) + cg1(&g_zbbq[1][i0]) +
                     cg1(&g_zbbq[2][i0]) + cg1(&g_zbbq[3][i0])) * vs[tid] +
                    (cg1(&zba[i1]) + cg1(&g_zbbq[0][i1]) + cg1(&g_zbbq[1][i1]) +
                     cg1(&g_zbbq[2][i1]) + cg1(&g_zbbq[3][i1])) * vs[256 + tid];
            }
            red[tid] = v;
            __syncthreads();
            for (int off = 128; off > 0; off >>= 1) {
                if (tid < off) red[tid] += red[tid + off];
                __syncthreads();
            }
            const float s = (red[0] > 0.f) ? 1.f : 0.f;
            if (tid == 0) g_s[b] = s;
            {
                const int j = tid << 2;
                const size_t o = (size_t)b * H_ + j;
                const float* z1 = g_z1_all + (size_t)t * B_ * H4_;
                const size_t z = (size_t)b * H4_ + j;
                float4 zi = cg4(&z1[z]);
                float4 zf = cg4(&z1[z + H_]);
                float4 zg = cg4(&z1[z + 2 * H_]);
                float4 zo = cg4(&z1[z + 3 * H_]);
                float xi[4] = {zi.x, zi.y, zi.z, zi.w};
                float xf[4] = {zf.x, zf.y, zf.z, zf.w};
                float xg[4] = {zg.x, zg.y, zg.z, zg.w};
                float xo[4] = {zo.x, zo.y, zo.z, zo.w};
                if (!h1z) {   // z1p valid only when P2 ran; otherwise contribution is exactly 0
#pragma unroll
                    for (int q4 = 0; q4 < 4; q4++) {
                        float4 pi = cg4(&g_z1p[q4][z]);
                        float4 pf = cg4(&g_z1p[q4][z + H_]);
                        float4 pg = cg4(&g_z1p[q4][z + 2 * H_]);
                        float4 po = cg4(&g_z1p[q4][z + 3 * H_]);
                        xi[0] += pi.x; xi[1] += pi.y; xi[2] += pi.z; xi[3] += pi.w;
                        xf[0] += pf.x; xf[1] += pf.y; xf[2] += pf.z; xf[3] += pf.w;
                        xg[0] += pg.x; xg[1] += pg.y; xg[2] += pg.z; xg[3] += pg.w;
                        xo[0] += po.x; xo[1] += po.y; xo[2] += po.z; xo[3] += po.w;
                    }
                }
                float4 c1v = *(const float4*)&g_c1[o];
                float cv[4] = {c1v.x, c1v.y, c1v.z, c1v.w};
                float x2v[4], h1v[4], c1n[4];
#pragma unroll
                for (int q = 0; q < 4; q++) {
                    float cn = sigf(xf[q]) * cv[q] + sigf(xi[q]) * tanhf(xg[q]);
                    float hn = sigf(xo[q]) * tanhf(cn);
                    x2v[q] = hn * s;
                    h1v[q] = hn * (1.f - s);
                    c1n[q] = cn * (1.f - s);
                }
                *(float4*)&g_x2[o] = make_float4(x2v[0], x2v[1], x2v[2], x2v[3]);
                *(float4*)&g_h1[o] = make_float4(h1v[0], h1v[1], h1v[2], h1v[3]);
                *(float4*)&g_c1[o] = make_float4(c1n[0], c1n[1], c1n[2], c1n[3]);
            }
        } else if (bid >= 168 && t > 0) {
            do_p6(bid - 168, t - 1, s_prev, out, out_flags);
        }
        grid_barrier(gen);

        const float s_cur = cg1(&g_s[0]);

        // ---- PHASE_A (XOR), all K=256 quarters:
        //      flagged -> P4: 384 tasks grid-strided over 296 blocks.
        //      unflagged -> P1': 96 tasks on blocks 0..95 (distinct SMs).
        if (s_cur > 0.5f) {
            for (int task = bid; task < 384; task += NBLK) {
                const int ct = task >> 2;
                const int kq = task & 3;
                const int koff = kq << 8;
                u64 acc[4][4] = {};
                if (ct < 16) {
                    const int c0 = ct << 6;
                    BufLoader bl{g_x2 + koff, H_};
                    gemm_seg(acc, bl, Wmx2 + (size_t)c0 * H_ + koff, 256, H_, As, Ws);
                    store_tile(g_mx2q[kq], H_, c0, acc, nullptr);
                } else if (ct < 32) {
                    const int c0 = (ct - 16) << 6;
                    BufLoader bl{g_h2 + koff, H_};
                    gemm_seg(acc, bl, Wmh2 + (size_t)c0 * H_ + koff, 256, H_, As, Ws);
                    store_tile(g_mh2q[kq], H_, c0, acc, nullptr);
                } else {
                    const int c0 = (ct - 32) << 6;
                    BufLoader bl{g_x2 + koff, H_};
                    gemm_seg(acc, bl, Wih2 + (size_t)c0 * H_ + koff, 256, H_, As, Ws);
                    store_tile(g_z2q[kq], H4_, c0, acc, (kq == 0) ? (b2 + c0) : nullptr);
                }
            }
        } else {
            if (bid < 96) {
                const int p  = bid >> 2;
                const int kq = bid & 3;
                const int koff = kq << 8;
                u64 acc[4][4] = {};
                BufLoader bl{g_h1 + koff, H_};
                if (p < 8) {
                    const int c0 = p << 6;
                    gemm_seg(acc, bl, Wsh + (size_t)c0 * H_ + koff, 256, H_, As, Ws);
                    store_tile(g_zbbq[kq], MID_, c0, acc, nullptr);
                } else {
                    const int c0 = (p - 8) << 6;
                    gemm_seg(acc, bl, Wmh1 + (size_t)c0 * H_ + koff, 256, H_, As, Ws);
                    store_tile(g_mhq[kq], H_, c0, acc, nullptr);
                }
            }
        }
        grid_barrier(gen);

        s_prev = s_cur;
        h1z = (s_cur > 0.5f);
    }

    // ---- epilogue: P5(S-1) if flagged, then P6(S-1), then final state copy.
    if (s_prev > 0.5f) {
        if (bid < 256) {
            const int c0 = (bid >> 2) << 6;
            const int kq = bid & 3;
            const int koff = kq << 8;
            u64 acc[4][4] = {};
            MulS44Loader ml{g_mx2q[0] + koff, g_mx2q[1] + koff, g_mx2q[2] + koff, g_mx2q[3] + koff,
                            g_mh2q[0] + koff, g_mh2q[1] + koff, g_mh2q[2] + koff, g_mh2q[3] + koff};
            gemm_seg(acc, ml, Whh2 + (size_t)c0 * H_ + koff, 256, H_, As, Ws);
            store_tile(g_z2p[kq], H4_, c0, acc, nullptr);
        }
        grid_barrier(gen);
    }
    if (bid >= 168) {
        do_p6(bid - 168, S_ - 1, s_prev, out, out_flags);
    }
    grid_barrier(gen);
    if (out_h2) {
        for (int i = bid * NTHR + tid; i < B_ * H_; i += NBLK * NTHR) {
            out_h2[i] = cg1(&g_h2[i]);
            out_c2[i] = cg1(&g_c2[i]);
        }
    }
}

// ---------------- host: exactly ONE graph node ----------------
extern "C" void kernel_launch(void* const* d_in, const int* in_sizes, int n_in,
                              void* d_out, int out_size) {
    const int*   enc   = (const int*)d_in[0];
    const int*   encx  = (const int*)d_in[1];
    const float* we    = (const float*)d_in[2];
    const float* ee    = (const float*)d_in[3];
    const float* Wsi   = (const float*)d_in[4];
    const float* Wsh   = (const float*)d_in[5];
    const float* b_bd  = (const float*)d_in[6];
    const float* vs    = (const float*)d_in[7];
    const float* Wmx1  = (const float*)d_in[8];
    const float* Wmh1  = (const float*)d_in[9];
    const float* Wih1  = (const float*)d_in[10];
    const float* Whh1  = (const float*)d_in[11];
    const float* b1    = (const float*)d_in[12];
    const float* Wmx2  = (const float*)d_in[13];
    const float* Wmh2  = (const float*)d_in[14];
    const float* Wih2  = (const float*)d_in[15];
    const float* Whh2  = (const float*)d_in[16];
    const float* b2    = (const float*)d_in[17];
    float* out = (float*)d_out;

    const size_t outs_elems  = (size_t)B_ * S_ * H_;
    const size_t state_elems = (size_t)B_ * H_;
    float* out_h2 = nullptr;
    float* out_c2 = nullptr;
    float* out_flags = nullptr;
    if ((size_t)out_size >= outs_elems + 2 * state_elems + S_) {
        out_h2 = out + outs_elems;
        out_c2 = out_h2 + state_elems;
        out_flags = out_c2 + state_elems;
    }

    enc_kernel<<<NBLK, NTHR>>>(enc, encx, we, ee, Wsi, Wsh, b_bd, vs,
                               Wmx1, Wmh1, Wih1, Whh1, b1,
                               Wmx2, Wmh2, Wih2, Whh2, b2,
                               out, out_h2, out_c2, out_flags);
    (void)in_sizes; (void)n_in;
}